// round 15
// baseline (speedup 1.0000x reference)
#include <cuda_runtime.h>
#include <cuda_bf16.h>
#include <cuda_fp16.h>
#include <math.h>
#include <stdint.h>

#define BB   4
#define SS_  1024
#define HIDD 1024
#define NH   16
#define NKH  8
#define HD   64
#define TOKENS (BB * SS_)   // 4096

// ---------------- scratch (no allocations allowed) ----------------
__device__ float g_qkv[(size_t)TOKENS * 2048];
__device__ float g_q[(size_t)BB * NH  * SS_ * HD];
__device__ float g_k[(size_t)BB * NKH * SS_ * HD];
__device__ float g_ao[(size_t)TOKENS * NH * HD];

__device__ __align__(256) __nv_bfloat16 g_ah [(size_t)TOKENS * 1024];
__device__ __align__(256) __nv_bfloat16 g_al [(size_t)TOKENS * 1024];
__device__ __align__(256) __nv_bfloat16 g_wth[(size_t)2048 * 1024];
__device__ __align__(256) __nv_bfloat16 g_wtl[(size_t)2048 * 1024];
__device__ __align__(256) __half        g_wof[(size_t)1024 * 1024];
__device__ __align__(256) __half        g_aofh[(size_t)TOKENS * 1024];
__device__ __align__(256) __half        g_aofl[(size_t)TOKENS * 1024];
__device__ __align__(256) __half        g_vth[(size_t)BB * NKH * HD * SS_]; // V^T fp16 [b][kh][d][s]

// ================= mma / ldmatrix helpers =================
__device__ __forceinline__ void mma_bf16(float* d, const unsigned* a, const unsigned* b)
{
    asm volatile(
        "mma.sync.aligned.m16n8k16.row.col.f32.bf16.bf16.f32 "
        "{%0,%1,%2,%3}, {%4,%5,%6,%7}, {%8,%9}, {%0,%1,%2,%3};\n"
        : "+f"(d[0]), "+f"(d[1]), "+f"(d[2]), "+f"(d[3])
        : "r"(a[0]), "r"(a[1]), "r"(a[2]), "r"(a[3]), "r"(b[0]), "r"(b[1]));
}
__device__ __forceinline__ void mma_f16r(float* d, const unsigned* a, const unsigned* b)
{
    asm volatile(
        "mma.sync.aligned.m16n8k16.row.col.f32.f16.f16.f32 "
        "{%0,%1,%2,%3}, {%4,%5,%6,%7}, {%8,%9}, {%0,%1,%2,%3};\n"
        : "+f"(d[0]), "+f"(d[1]), "+f"(d[2]), "+f"(d[3])
        : "r"(a[0]), "r"(a[1]), "r"(a[2]), "r"(a[3]), "r"(b[0]), "r"(b[1]));
}
__device__ __forceinline__ void ldsm_x4(unsigned* r, unsigned addr)
{
    asm volatile("ldmatrix.sync.aligned.m8n8.x4.shared.b16 {%0,%1,%2,%3}, [%4];\n"
                 : "=r"(r[0]), "=r"(r[1]), "=r"(r[2]), "=r"(r[3]) : "r"(addr));
}

// ================= converts =================
__global__ __launch_bounds__(256)
void convert_split(const float* __restrict__ X, __nv_bfloat16* __restrict__ H,
                   __nv_bfloat16* __restrict__ L, int n4)
{
    const int i = blockIdx.x * 256 + threadIdx.x;
    if (i >= n4) return;
    float4 v = ((const float4*)X)[i];
    __nv_bfloat162 h0 = __floats2bfloat162_rn(v.x, v.y);
    __nv_bfloat162 h1 = __floats2bfloat162_rn(v.z, v.w);
    __nv_bfloat162 l0 = __floats2bfloat162_rn(v.x - __bfloat162float(h0.x), v.y - __bfloat162float(h0.y));
    __nv_bfloat162 l1 = __floats2bfloat162_rn(v.z - __bfloat162float(h1.x), v.w - __bfloat162float(h1.y));
    *(__nv_bfloat162*)&H[(size_t)4 * i]     = h0;
    *(__nv_bfloat162*)&H[(size_t)4 * i + 2] = h1;
    *(__nv_bfloat162*)&L[(size_t)4 * i]     = l0;
    *(__nv_bfloat162*)&L[(size_t)4 * i + 2] = l1;
}

__global__ __launch_bounds__(256)
void convert_split_f16(const float* __restrict__ X, __half* __restrict__ H,
                       __half* __restrict__ L, int n4)
{
    const int i = blockIdx.x * 256 + threadIdx.x;
    if (i >= n4) return;
    float4 v = ((const float4*)X)[i];
    __half2 h0 = __floats2half2_rn(v.x, v.y);
    __half2 h1 = __floats2half2_rn(v.z, v.w);
    __half2 l0 = __floats2half2_rn(v.x - __half2float(__low2half(h0)), v.y - __half2float(__high2half(h0)));
    __half2 l1 = __floats2half2_rn(v.z - __half2float(__low2half(h1)), v.w - __half2float(__high2half(h1)));
    *(__half2*)&H[(size_t)4 * i]     = h0;
    *(__half2*)&H[(size_t)4 * i + 2] = h1;
    *(__half2*)&L[(size_t)4 * i]     = l0;
    *(__half2*)&L[(size_t)4 * i + 2] = l1;
}

// Merged weight transpose: Wq/Wk/Wv -> wth/wtl [n][1024 k] bf16 split, one launch.
__global__ __launch_bounds__(256)
void transpose_split3(const float* __restrict__ Wq, const float* __restrict__ Wk,
                      const float* __restrict__ Wv,
                      __nv_bfloat16* __restrict__ TH, __nv_bfloat16* __restrict__ TL)
{
    __shared__ float t[32][33];
    const int tx = threadIdx.x & 31;
    const int ty = threadIdx.x >> 5;
    const int xb = blockIdx.x;           // 0..63
    const int k0 = blockIdx.y * 32;

    const float* W;
    int N, n0;
    size_t obase;
    if (xb < 32)      { W = Wq; N = 1024; n0 = xb * 32;        obase = 0; }
    else if (xb < 48) { W = Wk; N = 512;  n0 = (xb - 32) * 32; obase = (size_t)1024 * 1024; }
    else              { W = Wv; N = 512;  n0 = (xb - 48) * 32; obase = (size_t)1536 * 1024; }

#pragma unroll
    for (int j = 0; j < 4; ++j)
        t[ty + 8 * j][tx] = W[(size_t)(k0 + ty + 8 * j) * N + n0 + tx];
    __syncthreads();
#pragma unroll
    for (int j = 0; j < 4; ++j) {
        const int n = ty + 8 * j;
        const float v = t[tx][n];
        const __nv_bfloat16 h = __float2bfloat16(v);
        TH[obase + (size_t)(n0 + n) * 1024 + k0 + tx] = h;
        TL[obase + (size_t)(n0 + n) * 1024 + k0 + tx] = __float2bfloat16(v - __bfloat162float(h));
    }
}

// Wo [1024 k][1024 n] fp32 -> T [n][1024 k] fp16 single
__global__ __launch_bounds__(256)
void transpose_f16(const float* __restrict__ W, __half* __restrict__ T, int N)
{
    __shared__ float t[32][33];
    const int tx = threadIdx.x & 31;
    const int ty = threadIdx.x >> 5;
    const int n0 = blockIdx.x * 32, k0 = blockIdx.y * 32;
#pragma unroll
    for (int j = 0; j < 4; ++j)
        t[ty + 8 * j][tx] = W[(size_t)(k0 + ty + 8 * j) * N + n0 + tx];
    __syncthreads();
#pragma unroll
    for (int j = 0; j < 4; ++j) {
        const int n = ty + 8 * j;
        T[(size_t)(n0 + n) * 1024 + k0 + tx] = __float2half_rn(t[tx][n]);
    }
}

// ================= bf16 3-pass GEMM, 2-stage pipeline, 2 CTAs/SM =================
#define PK 40
#define MAT_ELEMS (128 * PK)
#define STAGE_ELEMS (4 * MAT_ELEMS)
#define GEMM_SMEM (2 * STAGE_ELEMS * 2)        // 81920 -> 2 CTAs/SM

__global__ __launch_bounds__(256, 2)
void gemm_presplit(const __nv_bfloat16* __restrict__ Ah, const __nv_bfloat16* __restrict__ Al,
                   const __nv_bfloat16* __restrict__ Bh, const __nv_bfloat16* __restrict__ Bl,
                   float* __restrict__ C, int ldc)
{
    extern __shared__ __nv_bfloat16 sm[];

    const int tid  = threadIdx.x;
    const int lane = tid & 31;
    const int wid  = tid >> 5;
    const int wm   = wid & 3;
    const int wn   = wid >> 2;
    const int m0   = blockIdx.y * 128;
    const int n0   = blockIdx.x * 128;

    const __nv_bfloat16* srcs[4] = {
        Ah + (size_t)m0 * 1024, Al + (size_t)m0 * 1024,
        Bh + (size_t)n0 * 1024, Bl + (size_t)n0 * 1024 };

    const unsigned smb = (unsigned)__cvta_generic_to_shared(sm);

    auto stage = [&](int kb, int buf) {
        const unsigned dbase = smb + (unsigned)buf * STAGE_ELEMS * 2;
#pragma unroll
        for (int mat = 0; mat < 4; ++mat) {
            const __nv_bfloat16* s = srcs[mat];
            const unsigned mb = dbase + (unsigned)mat * MAT_ELEMS * 2;
#pragma unroll
            for (int j = 0; j < 2; ++j) {
                const int chunk = tid + j * 256;
                const int row   = chunk >> 2;
                const int c8    = (chunk & 3) * 8;
                const __nv_bfloat16* sp = s + (size_t)row * 1024 + kb * 32 + c8;
                const unsigned dst = mb + (unsigned)(row * PK + c8) * 2;
                asm volatile("cp.async.cg.shared.global [%0], [%1], 16;\n" :: "r"(dst), "l"(sp));
            }
        }
        asm volatile("cp.async.commit_group;\n" ::: "memory");
    };

    float acc[2][8][4];
#pragma unroll
    for (int i = 0; i < 2; ++i)
#pragma unroll
        for (int j = 0; j < 8; ++j)
#pragma unroll
            for (int t = 0; t < 4; ++t) acc[i][j][t] = 0.f;

    const unsigned aOff = (unsigned)((wm * 32 + (lane & 15)) * PK + (lane >> 4) * 8) * 2;
    const unsigned bOff = (unsigned)((wn * 64 + (lane & 15)) * PK + (lane >> 4) * 8) * 2;

    stage(0, 0);

    const int KB = 1024 / 32;
    for (int kb = 0; kb < KB; ++kb) {
        const int cur = kb & 1;
        if (kb + 1 < KB) {
            stage(kb + 1, cur ^ 1);
            asm volatile("cp.async.wait_group 1;\n" ::: "memory");
        } else {
            asm volatile("cp.async.wait_group 0;\n" ::: "memory");
        }
        __syncthreads();

        const unsigned base = smb + (unsigned)cur * STAGE_ELEMS * 2;
        const unsigned bAh = base;
        const unsigned bAl = base + MAT_ELEMS * 2;
        const unsigned bBh = base + 2 * MAT_ELEMS * 2;
        const unsigned bBl = base + 3 * MAT_ELEMS * 2;

#pragma unroll
        for (int kc = 0; kc < 2; ++kc) {
            const unsigned ko = (unsigned)(kc * 16) * 2;
            unsigned ah[2][4], al[2][4], bh[4][4], bl[4][4];
#pragma unroll
            for (int mt = 0; mt < 2; ++mt) {
                const unsigned o = aOff + (unsigned)(mt * 16 * PK) * 2 + ko;
                ldsm_x4(ah[mt], bAh + o);
                ldsm_x4(al[mt], bAl + o);
            }
#pragma unroll
            for (int nb = 0; nb < 4; ++nb) {
                const unsigned o = bOff + (unsigned)(nb * 16 * PK) * 2 + ko;
                ldsm_x4(bh[nb], bBh + o);
                ldsm_x4(bl[nb], bBl + o);
            }
#pragma unroll
            for (int mt = 0; mt < 2; ++mt)
#pragma unroll
                for (int nb = 0; nb < 4; ++nb) {
                    unsigned b0h[2] = { bh[nb][0], bh[nb][2] };
                    unsigned b1h[2] = { bh[nb][1], bh[nb][3] };
                    mma_bf16(acc[mt][2 * nb],     ah[mt], b0h);
                    mma_bf16(acc[mt][2 * nb + 1], ah[mt], b1h);
                }
#pragma unroll
            for (int mt = 0; mt < 2; ++mt)
#pragma unroll
                for (int nb = 0; nb < 4; ++nb) {
                    unsigned b0l[2] = { bl[nb][0], bl[nb][2] };
                    unsigned b1l[2] = { bl[nb][1], bl[nb][3] };
                    mma_bf16(acc[mt][2 * nb],     ah[mt], b0l);
                    mma_bf16(acc[mt][2 * nb + 1], ah[mt], b1l);
                }
#pragma unroll
            for (int mt = 0; mt < 2; ++mt)
#pragma unroll
                for (int nb = 0; nb < 4; ++nb) {
                    unsigned b0h[2] = { bh[nb][0], bh[nb][2] };
                    unsigned b1h[2] = { bh[nb][1], bh[nb][3] };
                    mma_bf16(acc[mt][2 * nb],     al[mt], b0h);
                    mma_bf16(acc[mt][2 * nb + 1], al[mt], b1h);
                }
        }
        __syncthreads();
    }

    const int crow0 = m0 + wm * 32 + (lane >> 2);
    const int ccol0 = n0 + wn * 64 + (lane & 3) * 2;
#pragma unroll
    for (int mt = 0; mt < 2; ++mt)
#pragma unroll
        for (int nt = 0; nt < 8; ++nt) {
            float* p0 = C + (size_t)(crow0 + mt * 16) * ldc + ccol0 + nt * 8;
            float* p1 = p0 + 8 * ldc;
            *(float2*)p0 = make_float2(acc[mt][nt][0], acc[mt][nt][1]);
            *(float2*)p1 = make_float2(acc[mt][nt][2], acc[mt][nt][3]);
        }
}

// ================= fp16 2-pass GEMM, 2-stage pipeline, 2 CTAs/SM =================
#define MAT3_STAGE (3 * MAT_ELEMS)
#define GEMM16_SMEM (2 * MAT3_STAGE * 2)       // 61440 -> 2 CTAs/SM

__global__ __launch_bounds__(256, 2)
void gemm_fp16x2(const __half* __restrict__ Ah, const __half* __restrict__ Al,
                 const __half* __restrict__ Bf,
                 float* __restrict__ C, int ldc)
{
    extern __shared__ __half sm16[];

    const int tid  = threadIdx.x;
    const int lane = tid & 31;
    const int wid  = tid >> 5;
    const int wm   = wid & 3;
    const int wn   = wid >> 2;
    const int m0   = blockIdx.y * 128;
    const int n0   = blockIdx.x * 128;

    const __half* srcs[3] = {
        Ah + (size_t)m0 * 1024, Al + (size_t)m0 * 1024, Bf + (size_t)n0 * 1024 };

    const unsigned smb = (unsigned)__cvta_generic_to_shared(sm16);

    auto stage = [&](int kb, int buf) {
        const unsigned dbase = smb + (unsigned)buf * MAT3_STAGE * 2;
#pragma unroll
        for (int mat = 0; mat < 3; ++mat) {
            const __half* s = srcs[mat];
            const unsigned mb = dbase + (unsigned)mat * MAT_ELEMS * 2;
#pragma unroll
            for (int j = 0; j < 2; ++j) {
                const int chunk = tid + j * 256;
                const int row   = chunk >> 2;
                const int c8    = (chunk & 3) * 8;
                const __half* sp = s + (size_t)row * 1024 + kb * 32 + c8;
                const unsigned dst = mb + (unsigned)(row * PK + c8) * 2;
                asm volatile("cp.async.cg.shared.global [%0], [%1], 16;\n" :: "r"(dst), "l"(sp));
            }
        }
        asm volatile("cp.async.commit_group;\n" ::: "memory");
    };

    float acc[2][8][4];
#pragma unroll
    for (int i = 0; i < 2; ++i)
#pragma unroll
        for (int j = 0; j < 8; ++j)
#pragma unroll
            for (int t = 0; t < 4; ++t) acc[i][j][t] = 0.f;

    const unsigned aOff = (unsigned)((wm * 32 + (lane & 15)) * PK + (lane >> 4) * 8) * 2;
    const unsigned bOff = (unsigned)((wn * 64 + (lane & 15)) * PK + (lane >> 4) * 8) * 2;

    stage(0, 0);

    const int KB = 1024 / 32;
    for (int kb = 0; kb < KB; ++kb) {
        const int cur = kb & 1;
        if (kb + 1 < KB) {
            stage(kb + 1, cur ^ 1);
            asm volatile("cp.async.wait_group 1;\n" ::: "memory");
        } else {
            asm volatile("cp.async.wait_group 0;\n" ::: "memory");
        }
        __syncthreads();

        const unsigned base = smb + (unsigned)cur * MAT3_STAGE * 2;
        const unsigned bAh = base;
        const unsigned bAl = base + MAT_ELEMS * 2;
        const unsigned bBf = base + 2 * MAT_ELEMS * 2;

#pragma unroll
        for (int kc = 0; kc < 2; ++kc) {
            const unsigned ko = (unsigned)(kc * 16) * 2;
            unsigned ah[2][4], al[2][4], bf4[4][4];
#pragma unroll
            for (int mt = 0; mt < 2; ++mt) {
                const unsigned o = aOff + (unsigned)(mt * 16 * PK) * 2 + ko;
                ldsm_x4(ah[mt], bAh + o);
                ldsm_x4(al[mt], bAl + o);
            }
#pragma unroll
            for (int nb = 0; nb < 4; ++nb) {
                const unsigned o = bOff + (unsigned)(nb * 16 * PK) * 2 + ko;
                ldsm_x4(bf4[nb], bBf + o);
            }
#pragma unroll
            for (int mt = 0; mt < 2; ++mt)
#pragma unroll
                for (int nb = 0; nb < 4; ++nb) {
                    unsigned b0[2] = { bf4[nb][0], bf4[nb][2] };
                    unsigned b1[2] = { bf4[nb][1], bf4[nb][3] };
                    mma_f16r(acc[mt][2 * nb],     ah[mt], b0);
                    mma_f16r(acc[mt][2 * nb + 1], ah[mt], b1);
                }
#pragma unroll
            for (int mt = 0; mt < 2; ++mt)
#pragma unroll
                for (int nb = 0; nb < 4; ++nb) {
                    unsigned b0[2] = { bf4[nb][0], bf4[nb][2] };
                    unsigned b1[2] = { bf4[nb][1], bf4[nb][3] };
                    mma_f16r(acc[mt][2 * nb],     al[mt], b0);
                    mma_f16r(acc[mt][2 * nb + 1], al[mt], b1);
                }
        }
        __syncthreads();
    }

    const int crow0 = m0 + wm * 32 + (lane >> 2);
    const int ccol0 = n0 + wn * 64 + (lane & 3) * 2;
#pragma unroll
    for (int mt = 0; mt < 2; ++mt)
#pragma unroll
        for (int nt = 0; nt < 8; ++nt) {
            float* p0 = C + (size_t)(crow0 + mt * 16) * ldc + ccol0 + nt * 8;
            float* p1 = p0 + 8 * ldc;
            *(float2*)p0 = make_float2(acc[mt][nt][0], acc[mt][nt][1]);
            *(float2*)p1 = make_float2(acc[mt][nt][2], acc[mt][nt][3]);
        }
}

// ---------------- RMSNorm + 2D RoPE epilogue (V -> fp16 transposed) ----------------
__global__ __launch_bounds__(256)
void qkv_epilogue(const float* __restrict__ qkv,
                  const float* __restrict__ qg, const float* __restrict__ kg,
                  const int* __restrict__ pos,
                  float* __restrict__ q, float* __restrict__ k, __half* __restrict__ vt)
{
    const int w     = (blockIdx.x * blockDim.x + threadIdx.x) >> 5;
    const int lane  = threadIdx.x & 31;
    const int token = w >> 5;
    const int row   = w & 31;
    const int b     = token >> 10;
    const int s     = token & 1023;

    const float* src;
    float* dst = nullptr;
    __half* vdst = nullptr;
    const float* gamma = nullptr;
    bool rope = true;
    if (row < 16) {
        src = qkv + (size_t)token * 2048 + row * 64;
        dst = q + ((size_t)(b * NH + row) * SS_ + s) * HD;
        gamma = qg;
    } else if (row < 24) {
        const int h = row - 16;
        src = qkv + (size_t)token * 2048 + 1024 + h * 64;
        dst = k + ((size_t)(b * NKH + h) * SS_ + s) * HD;
        gamma = kg;
    } else {
        const int h = row - 24;
        src = qkv + (size_t)token * 2048 + 1536 + h * 64;
        vdst = vt + ((size_t)(b * NKH + h) * HD) * SS_ + s;
        rope = false;
    }

    float x0 = src[lane];
    float x1 = src[lane + 32];
    float ssum = x0 * x0 + x1 * x1;
#pragma unroll
    for (int off = 16; off; off >>= 1)
        ssum += __shfl_xor_sync(0xffffffffu, ssum, off);
    const float r = rsqrtf(ssum * (1.0f / 64.0f) + 1e-6f);
    x0 *= r; x1 *= r;
    if (gamma) {
        x0 *= 1.0f + gamma[lane];
        x1 *= 1.0f + gamma[lane + 32];
    }
    if (rope) {
        const float px = (float)pos[token * 2 + 0];
        const float py = (float)pos[token * 2 + 1];
        const int j = lane & 15;
        const float invf = exp2f(-13.2877123795494f * (float)j * (1.0f / 16.0f));
        float s0, c0, s1, c1;
        sincosf(px * invf, &s0, &c0);
        sincosf(py * invf, &s1, &c1);
        const float p0 = __shfl_xor_sync(0xffffffffu, x0, 16);
        const float p1 = __shfl_xor_sync(0xffffffffu, x1, 16);
        if (lane < 16) { x0 = x0 * c0 - p0 * s0; x1 = x1 * c1 - p1 * s1; }
        else           { x0 = x0 * c0 + p0 * s0; x1 = x1 * c1 + p1 * s1; }
        dst[lane]      = x0;
        dst[lane + 32] = x1;
    } else {
        vdst[(size_t)lane * SS_]        = __float2half_rn(x0);
        vdst[(size_t)(lane + 32) * SS_] = __float2half_rn(x1);
    }
}

// ================= flash attention (R10 math, uncapped occupancy) =================
__device__ __forceinline__ void fsplit_bf16(float x, float y, unsigned& hi, unsigned& lo)
{
    __nv_bfloat162 h = __floats2bfloat162_rn(x, y);
    hi = *(unsigned*)&h;
    __nv_bfloat162 l = __floats2bfloat162_rn(x - __bfloat162float(h.x), y - __bfloat162float(h.y));
    lo = *(unsigned*)&l;
}

__global__ __launch_bounds__(256)
void flash_attn_mma(const float* __restrict__ gq, const float* __restrict__ gk,
                    const __half* __restrict__ gvt, float* __restrict__ ao)
{
    const int lane = threadIdx.x & 31;
    const int w    = threadIdx.x >> 5;
    const int bh   = blockIdx.y;
    const int b    = bh >> 4;
    const int h    = bh & 15;
    const int kh   = h >> 1;
    const int q0   = blockIdx.x * 128 + w * 16;

    const int r  = lane >> 2;
    const int cq = (lane & 3) * 2;

    const float* qb = gq  + ((size_t)(b * NH  + h ) * SS_ + q0) * HD;
    const float* kb = gk  + ((size_t)(b * NKH + kh) * SS_) * HD;
    const __half* vt = gvt + ((size_t)(b * NKH + kh) * HD) * SS_;

    unsigned qh[4][4], ql[4][4];
#pragma unroll
    for (int kc = 0; kc < 4; ++kc)
#pragma unroll
        for (int i = 0; i < 4; ++i) {
            const int row = r + (i & 1) * 8;
            const int col = kc * 16 + cq + (i & 2) * 4;
            float2 t = *(const float2*)(qb + (size_t)row * HD + col);
            fsplit_bf16(t.x, t.y, qh[kc][i], ql[kc][i]);
        }

    float o[8][4];
#pragma unroll
    for (int nt = 0; nt < 8; ++nt)
#pragma unroll
        for (int j = 0; j < 4; ++j) o[nt][j] = 0.f;
    float m0 = -1e30f, m1 = -1e30f, l0 = 0.f, l1 = 0.f;

    for (int kt = 0; kt < 16; ++kt) {
        const float* kp = kb + (size_t)kt * 64 * HD;

        float s[8][4];
#pragma unroll
        for (int nt = 0; nt < 8; ++nt)
#pragma unroll
            for (int j = 0; j < 4; ++j) s[nt][j] = 0.f;

#pragma unroll
        for (int kc = 0; kc < 4; ++kc) {
            unsigned kfh[8][2], kfl[8][2];
#pragma unroll
            for (int nt = 0; nt < 8; ++nt) {
                const float* rowp = kp + (size_t)(nt * 8 + r) * HD + kc * 16 + cq;
                float2 t0 = *(const float2*)rowp;
                float2 t1 = *(const float2*)(rowp + 8);
                fsplit_bf16(t0.x, t0.y, kfh[nt][0], kfl[nt][0]);
                fsplit_bf16(t1.x, t1.y, kfh[nt][1], kfl[nt][1]);
            }
#pragma unroll
            for (int nt = 0; nt < 8; ++nt)
                mma_bf16(s[nt], qh[kc], kfh[nt]);
#pragma unroll
            for (int nt = 0; nt < 8; ++nt)
                mma_bf16(s[nt], qh[kc], kfl[nt]);
#pragma unroll
            for (int nt = 0; nt < 8; ++nt)
                mma_bf16(s[nt], ql[kc], kfh[nt]);
        }

        float mx0 = s[0][0], mx1 = s[0][2];
#pragma unroll
        for (int nt = 0; nt < 8; ++nt) {
            mx0 = fmaxf(mx0, fmaxf(s[nt][0], s[nt][1]));
            mx1 = fmaxf(mx1, fmaxf(s[nt][2], s[nt][3]));
        }
        mx0 = fmaxf(mx0, __shfl_xor_sync(0xffffffffu, mx0, 1));
        mx0 = fmaxf(mx0, __shfl_xor_sync(0xffffffffu, mx0, 2));
        mx1 = fmaxf(mx1, __shfl_xor_sync(0xffffffffu, mx1, 1));
        mx1 = fmaxf(mx1, __shfl_xor_sync(0xffffffffu, mx1, 2));

        const float mn0 = fmaxf(m0, mx0);
        const float mn1 = fmaxf(m1, mx1);
        const float al0 = __expf(m0 - mn0);
        const float al1 = __expf(m1 - mn1);
        m0 = mn0; m1 = mn1;

        float rs0 = 0.f, rs1 = 0.f;
#pragma unroll
        for (int nt = 0; nt < 8; ++nt) {
            s[nt][0] = __expf(s[nt][0] - mn0);
            s[nt][1] = __expf(s[nt][1] - mn0);
            s[nt][2] = __expf(s[nt][2] - mn1);
            s[nt][3] = __expf(s[nt][3] - mn1);
            rs0 += s[nt][0] + s[nt][1];
            rs1 += s[nt][2] + s[nt][3];
        }
        rs0 += __shfl_xor_sync(0xffffffffu, rs0, 1);
        rs0 += __shfl_xor_sync(0xffffffffu, rs0, 2);
        rs1 += __shfl_xor_sync(0xffffffffu, rs1, 1);
        rs1 += __shfl_xor_sync(0xffffffffu, rs1, 2);
        l0 = l0 * al0 + rs0;
        l1 = l1 * al1 + rs1;

#pragma unroll
        for (int nt = 0; nt < 8; ++nt) {
            o[nt][0] *= al0; o[nt][1] *= al0;
            o[nt][2] *= al1; o[nt][3] *= al1;
        }

#pragma unroll
        for (int kc = 0; kc < 4; ++kc) {
            unsigned pa[4];
            {
                __half2 t;
                t = __floats2half2_rn(s[2 * kc][0],     s[2 * kc][1]);     pa[0] = *(unsigned*)&t;
                t = __floats2half2_rn(s[2 * kc][2],     s[2 * kc][3]);     pa[1] = *(unsigned*)&t;
                t = __floats2half2_rn(s[2 * kc + 1][0], s[2 * kc + 1][1]); pa[2] = *(unsigned*)&t;
                t = __floats2half2_rn(s[2 * kc + 1][2], s[2 * kc + 1][3]); pa[3] = *(unsigned*)&t;
            }
#pragma unroll
            for (int ntd = 0; ntd < 8; ++ntd) {
                const size_t off = (size_t)(ntd * 8 + r) * SS_ + kt * 64 + kc * 16 + cq;
                unsigned vh2[2];
                vh2[0] = *(const unsigned*)(vt + off);
                vh2[1] = *(const unsigned*)(vt + off + 8);
                mma_f16r(o[ntd], pa, vh2);
            }
        }
    }

    const float inv0 = 1.0f / l0;
    const float inv1 = 1.0f / l1;
    const int sg0 = q0 + r;
    const int sg1 = q0 + r + 8;
    float* a0 = ao + (((size_t)b * SS_ + sg0) * NH + h) * HD;
    float* a1 = ao + (((size_t)b * SS_ + sg1) * NH + h) * HD;
#pragma unroll
    for (int ntd = 0; ntd < 8; ++ntd) {
        *(float2*)(a0 + ntd * 8 + cq) = make_float2(o[ntd][0] * inv0, o[ntd][1] * inv0);
        *(float2*)(a1 + ntd * 8 + cq) = make_float2(o[ntd][2] * inv1, o[ntd][3] * inv1);
    }
}

// ---------------- launch ----------------
extern "C" void kernel_launch(void* const* d_in, const int* in_sizes, int n_in,
                              void* d_out, int out_size)
{
    (void)in_sizes; (void)n_in; (void)out_size;
    const float* hidden = (const float*)d_in[0];
    const float* Wq     = (const float*)d_in[1];
    const float* Wk     = (const float*)d_in[2];
    const float* Wv     = (const float*)d_in[3];
    const float* Wo     = (const float*)d_in[4];
    const float* qg     = (const float*)d_in[5];
    const float* kg     = (const float*)d_in[6];
    const int*   pos    = (const int*)d_in[7];
    float* out = (float*)d_out;

    float *qkv, *q, *k, *ao;
    __nv_bfloat16 *ah, *al, *wth, *wtl;
    __half *wof, *aofh, *aofl, *vth;
    cudaGetSymbolAddress((void**)&qkv,  g_qkv);
    cudaGetSymbolAddress((void**)&q,    g_q);
    cudaGetSymbolAddress((void**)&k,    g_k);
    cudaGetSymbolAddress((void**)&ao,   g_ao);
    cudaGetSymbolAddress((void**)&ah,   g_ah);
    cudaGetSymbolAddress((void**)&al,   g_al);
    cudaGetSymbolAddress((void**)&wth,  g_wth);
    cudaGetSymbolAddress((void**)&wtl,  g_wtl);
    cudaGetSymbolAddress((void**)&wof,  g_wof);
    cudaGetSymbolAddress((void**)&aofh, g_aofh);
    cudaGetSymbolAddress((void**)&aofl, g_aofl);
    cudaGetSymbolAddress((void**)&vth,  g_vth);

    cudaFuncSetAttribute(gemm_presplit, cudaFuncAttributeMaxDynamicSharedMemorySize, GEMM_SMEM);
    cudaFuncSetAttribute(gemm_fp16x2,   cudaFuncAttributeMaxDynamicSharedMemorySize, GEMM16_SMEM);

    const dim3 blk(256);

    // 1: hidden split
    convert_split<<<TOKENS * 1024 / 4 / 256, blk>>>(hidden, ah, al, TOKENS * 1024 / 4);
    // 2: Wo fp16 transpose
    transpose_f16<<<dim3(32, 32), blk>>>(Wo, wof, 1024);
    // 3: merged Wq/Wk/Wv transpose-split
    transpose_split3<<<dim3(64, 32), blk>>>(Wq, Wk, Wv, wth, wtl);
    // 4: fused QKV GEMM (ncu capture position)
    gemm_presplit<<<dim3(16, 32), blk, GEMM_SMEM>>>(ah, al, wth, wtl, qkv, 2048);
    // 5: RMSNorm + RoPE; V -> fp16 transposed
    qkv_epilogue<<<TOKENS * 32 / 8, blk>>>(qkv, qg, kg, pos, q, k, vth);
    // 6: attention (uncapped occupancy, fp32 AO out)
    flash_attn_mma<<<dim3(SS_ / 128, BB * NH), blk>>>(q, k, vth, ao);
    // 7: AO fp16 split
    convert_split_f16<<<TOKENS * 1024 / 4 / 256, blk>>>(ao, aofh, aofl, TOKENS * 1024 / 4);
    // 8: O projection
    gemm_fp16x2<<<dim3(8, 32), blk, GEMM16_SMEM>>>(aofh, aofl, wof, out, 1024);
}

// round 16
// speedup vs baseline: 1.1132x; 1.1132x over previous
#include <cuda_runtime.h>
#include <cuda_bf16.h>
#include <cuda_fp16.h>
#include <math.h>
#include <stdint.h>

#define BB   4
#define SS_  1024
#define HIDD 1024
#define NH   16
#define NKH  8
#define HD   64
#define TOKENS (BB * SS_)   // 4096

// ---------------- scratch (no allocations allowed) ----------------
__device__ float g_qkv[(size_t)TOKENS * 2048];
__device__ float g_q[(size_t)BB * NH  * SS_ * HD];
__device__ float g_k[(size_t)BB * NKH * SS_ * HD];
__device__ float g_ao[(size_t)TOKENS * NH * HD];

__device__ __align__(256) __nv_bfloat16 g_ah [(size_t)TOKENS * 1024];
__device__ __align__(256) __nv_bfloat16 g_al [(size_t)TOKENS * 1024];
__device__ __align__(256) __nv_bfloat16 g_wth[(size_t)2048 * 1024];
__device__ __align__(256) __nv_bfloat16 g_wtl[(size_t)2048 * 1024];
__device__ __align__(256) __half        g_wof[(size_t)1024 * 1024];
__device__ __align__(256) __half        g_aofh[(size_t)TOKENS * 1024];
__device__ __align__(256) __half        g_aofl[(size_t)TOKENS * 1024];
__device__ __align__(256) __half        g_vth[(size_t)BB * NKH * HD * SS_]; // V^T fp16 [b][kh][d][s]

// ================= mma / ldmatrix helpers =================
__device__ __forceinline__ void mma_bf16(float* d, const unsigned* a, const unsigned* b)
{
    asm volatile(
        "mma.sync.aligned.m16n8k16.row.col.f32.bf16.bf16.f32 "
        "{%0,%1,%2,%3}, {%4,%5,%6,%7}, {%8,%9}, {%0,%1,%2,%3};\n"
        : "+f"(d[0]), "+f"(d[1]), "+f"(d[2]), "+f"(d[3])
        : "r"(a[0]), "r"(a[1]), "r"(a[2]), "r"(a[3]), "r"(b[0]), "r"(b[1]));
}
__device__ __forceinline__ void mma_f16r(float* d, const unsigned* a, const unsigned* b)
{
    asm volatile(
        "mma.sync.aligned.m16n8k16.row.col.f32.f16.f16.f32 "
        "{%0,%1,%2,%3}, {%4,%5,%6,%7}, {%8,%9}, {%0,%1,%2,%3};\n"
        : "+f"(d[0]), "+f"(d[1]), "+f"(d[2]), "+f"(d[3])
        : "r"(a[0]), "r"(a[1]), "r"(a[2]), "r"(a[3]), "r"(b[0]), "r"(b[1]));
}
__device__ __forceinline__ void ldsm_x4(unsigned* r, unsigned addr)
{
    asm volatile("ldmatrix.sync.aligned.m8n8.x4.shared.b16 {%0,%1,%2,%3}, [%4];\n"
                 : "=r"(r[0]), "=r"(r[1]), "=r"(r[2]), "=r"(r[3]) : "r"(addr));
}

// ================= converts =================
__global__ __launch_bounds__(256)
void convert_split(const float* __restrict__ X, __nv_bfloat16* __restrict__ H,
                   __nv_bfloat16* __restrict__ L, int n4)
{
    const int i = blockIdx.x * 256 + threadIdx.x;
    if (i >= n4) return;
    float4 v = ((const float4*)X)[i];
    __nv_bfloat162 h0 = __floats2bfloat162_rn(v.x, v.y);
    __nv_bfloat162 h1 = __floats2bfloat162_rn(v.z, v.w);
    __nv_bfloat162 l0 = __floats2bfloat162_rn(v.x - __bfloat162float(h0.x), v.y - __bfloat162float(h0.y));
    __nv_bfloat162 l1 = __floats2bfloat162_rn(v.z - __bfloat162float(h1.x), v.w - __bfloat162float(h1.y));
    *(__nv_bfloat162*)&H[(size_t)4 * i]     = h0;
    *(__nv_bfloat162*)&H[(size_t)4 * i + 2] = h1;
    *(__nv_bfloat162*)&L[(size_t)4 * i]     = l0;
    *(__nv_bfloat162*)&L[(size_t)4 * i + 2] = l1;
}

__global__ __launch_bounds__(256)
void convert_split_f16(const float* __restrict__ X, __half* __restrict__ H,
                       __half* __restrict__ L, int n4)
{
    const int i = blockIdx.x * 256 + threadIdx.x;
    if (i >= n4) return;
    float4 v = ((const float4*)X)[i];
    __half2 h0 = __floats2half2_rn(v.x, v.y);
    __half2 h1 = __floats2half2_rn(v.z, v.w);
    __half2 l0 = __floats2half2_rn(v.x - __half2float(__low2half(h0)), v.y - __half2float(__high2half(h0)));
    __half2 l1 = __floats2half2_rn(v.z - __half2float(__low2half(h1)), v.w - __half2float(__high2half(h1)));
    *(__half2*)&H[(size_t)4 * i]     = h0;
    *(__half2*)&H[(size_t)4 * i + 2] = h1;
    *(__half2*)&L[(size_t)4 * i]     = l0;
    *(__half2*)&L[(size_t)4 * i + 2] = l1;
}

// Merged weight transpose: Wq/Wk/Wv -> wth/wtl [n][1024 k] bf16 split, one launch.
__global__ __launch_bounds__(256)
void transpose_split3(const float* __restrict__ Wq, const float* __restrict__ Wk,
                      const float* __restrict__ Wv,
                      __nv_bfloat16* __restrict__ TH, __nv_bfloat16* __restrict__ TL)
{
    __shared__ float t[32][33];
    const int tx = threadIdx.x & 31;
    const int ty = threadIdx.x >> 5;
    const int xb = blockIdx.x;           // 0..63
    const int k0 = blockIdx.y * 32;

    const float* W;
    int N, n0;
    size_t obase;
    if (xb < 32)      { W = Wq; N = 1024; n0 = xb * 32;        obase = 0; }
    else if (xb < 48) { W = Wk; N = 512;  n0 = (xb - 32) * 32; obase = (size_t)1024 * 1024; }
    else              { W = Wv; N = 512;  n0 = (xb - 48) * 32; obase = (size_t)1536 * 1024; }

#pragma unroll
    for (int j = 0; j < 4; ++j)
        t[ty + 8 * j][tx] = W[(size_t)(k0 + ty + 8 * j) * N + n0 + tx];
    __syncthreads();
#pragma unroll
    for (int j = 0; j < 4; ++j) {
        const int n = ty + 8 * j;
        const float v = t[tx][n];
        const __nv_bfloat16 h = __float2bfloat16(v);
        TH[obase + (size_t)(n0 + n) * 1024 + k0 + tx] = h;
        TL[obase + (size_t)(n0 + n) * 1024 + k0 + tx] = __float2bfloat16(v - __bfloat162float(h));
    }
}

// Wo [1024 k][1024 n] fp32 -> T [n][1024 k] fp16 single
__global__ __launch_bounds__(256)
void transpose_f16(const float* __restrict__ W, __half* __restrict__ T, int N)
{
    __shared__ float t[32][33];
    const int tx = threadIdx.x & 31;
    const int ty = threadIdx.x >> 5;
    const int n0 = blockIdx.x * 32, k0 = blockIdx.y * 32;
#pragma unroll
    for (int j = 0; j < 4; ++j)
        t[ty + 8 * j][tx] = W[(size_t)(k0 + ty + 8 * j) * N + n0 + tx];
    __syncthreads();
#pragma unroll
    for (int j = 0; j < 4; ++j) {
        const int n = ty + 8 * j;
        T[(size_t)(n0 + n) * 1024 + k0 + tx] = __float2half_rn(t[tx][n]);
    }
}

// ================= bf16 3-pass GEMM, 2-stage pipeline, 2 CTAs/SM =================
#define PK 40
#define MAT_ELEMS (128 * PK)
#define STAGE_ELEMS (4 * MAT_ELEMS)
#define GEMM_SMEM (2 * STAGE_ELEMS * 2)        // 81920 -> 2 CTAs/SM

__global__ __launch_bounds__(256, 2)
void gemm_presplit(const __nv_bfloat16* __restrict__ Ah, const __nv_bfloat16* __restrict__ Al,
                   const __nv_bfloat16* __restrict__ Bh, const __nv_bfloat16* __restrict__ Bl,
                   float* __restrict__ C, int ldc)
{
    extern __shared__ __nv_bfloat16 sm[];

    const int tid  = threadIdx.x;
    const int lane = tid & 31;
    const int wid  = tid >> 5;
    const int wm   = wid & 3;
    const int wn   = wid >> 2;
    const int m0   = blockIdx.y * 128;
    const int n0   = blockIdx.x * 128;

    const __nv_bfloat16* srcs[4] = {
        Ah + (size_t)m0 * 1024, Al + (size_t)m0 * 1024,
        Bh + (size_t)n0 * 1024, Bl + (size_t)n0 * 1024 };

    const unsigned smb = (unsigned)__cvta_generic_to_shared(sm);

    auto stage = [&](int kb, int buf) {
        const unsigned dbase = smb + (unsigned)buf * STAGE_ELEMS * 2;
#pragma unroll
        for (int mat = 0; mat < 4; ++mat) {
            const __nv_bfloat16* s = srcs[mat];
            const unsigned mb = dbase + (unsigned)mat * MAT_ELEMS * 2;
#pragma unroll
            for (int j = 0; j < 2; ++j) {
                const int chunk = tid + j * 256;
                const int row   = chunk >> 2;
                const int c8    = (chunk & 3) * 8;
                const __nv_bfloat16* sp = s + (size_t)row * 1024 + kb * 32 + c8;
                const unsigned dst = mb + (unsigned)(row * PK + c8) * 2;
                asm volatile("cp.async.cg.shared.global [%0], [%1], 16;\n" :: "r"(dst), "l"(sp));
            }
        }
        asm volatile("cp.async.commit_group;\n" ::: "memory");
    };

    float acc[2][8][4];
#pragma unroll
    for (int i = 0; i < 2; ++i)
#pragma unroll
        for (int j = 0; j < 8; ++j)
#pragma unroll
            for (int t = 0; t < 4; ++t) acc[i][j][t] = 0.f;

    const unsigned aOff = (unsigned)((wm * 32 + (lane & 15)) * PK + (lane >> 4) * 8) * 2;
    const unsigned bOff = (unsigned)((wn * 64 + (lane & 15)) * PK + (lane >> 4) * 8) * 2;

    stage(0, 0);

    const int KB = 1024 / 32;
    for (int kb = 0; kb < KB; ++kb) {
        const int cur = kb & 1;
        if (kb + 1 < KB) {
            stage(kb + 1, cur ^ 1);
            asm volatile("cp.async.wait_group 1;\n" ::: "memory");
        } else {
            asm volatile("cp.async.wait_group 0;\n" ::: "memory");
        }
        __syncthreads();

        const unsigned base = smb + (unsigned)cur * STAGE_ELEMS * 2;
        const unsigned bAh = base;
        const unsigned bAl = base + MAT_ELEMS * 2;
        const unsigned bBh = base + 2 * MAT_ELEMS * 2;
        const unsigned bBl = base + 3 * MAT_ELEMS * 2;

#pragma unroll
        for (int kc = 0; kc < 2; ++kc) {
            const unsigned ko = (unsigned)(kc * 16) * 2;
            unsigned ah[2][4], al[2][4], bh[4][4], bl[4][4];
#pragma unroll
            for (int mt = 0; mt < 2; ++mt) {
                const unsigned o = aOff + (unsigned)(mt * 16 * PK) * 2 + ko;
                ldsm_x4(ah[mt], bAh + o);
                ldsm_x4(al[mt], bAl + o);
            }
#pragma unroll
            for (int nb = 0; nb < 4; ++nb) {
                const unsigned o = bOff + (unsigned)(nb * 16 * PK) * 2 + ko;
                ldsm_x4(bh[nb], bBh + o);
                ldsm_x4(bl[nb], bBl + o);
            }
#pragma unroll
            for (int mt = 0; mt < 2; ++mt)
#pragma unroll
                for (int nb = 0; nb < 4; ++nb) {
                    unsigned b0h[2] = { bh[nb][0], bh[nb][2] };
                    unsigned b1h[2] = { bh[nb][1], bh[nb][3] };
                    mma_bf16(acc[mt][2 * nb],     ah[mt], b0h);
                    mma_bf16(acc[mt][2 * nb + 1], ah[mt], b1h);
                }
#pragma unroll
            for (int mt = 0; mt < 2; ++mt)
#pragma unroll
                for (int nb = 0; nb < 4; ++nb) {
                    unsigned b0l[2] = { bl[nb][0], bl[nb][2] };
                    unsigned b1l[2] = { bl[nb][1], bl[nb][3] };
                    mma_bf16(acc[mt][2 * nb],     ah[mt], b0l);
                    mma_bf16(acc[mt][2 * nb + 1], ah[mt], b1l);
                }
#pragma unroll
            for (int mt = 0; mt < 2; ++mt)
#pragma unroll
                for (int nb = 0; nb < 4; ++nb) {
                    unsigned b0h[2] = { bh[nb][0], bh[nb][2] };
                    unsigned b1h[2] = { bh[nb][1], bh[nb][3] };
                    mma_bf16(acc[mt][2 * nb],     al[mt], b0h);
                    mma_bf16(acc[mt][2 * nb + 1], al[mt], b1h);
                }
        }
        __syncthreads();
    }

    const int crow0 = m0 + wm * 32 + (lane >> 2);
    const int ccol0 = n0 + wn * 64 + (lane & 3) * 2;
#pragma unroll
    for (int mt = 0; mt < 2; ++mt)
#pragma unroll
        for (int nt = 0; nt < 8; ++nt) {
            float* p0 = C + (size_t)(crow0 + mt * 16) * ldc + ccol0 + nt * 8;
            float* p1 = p0 + 8 * ldc;
            *(float2*)p0 = make_float2(acc[mt][nt][0], acc[mt][nt][1]);
            *(float2*)p1 = make_float2(acc[mt][nt][2], acc[mt][nt][3]);
        }
}

// ================= fp16 2-pass GEMM, 2-stage pipeline, 2 CTAs/SM =================
#define MAT3_STAGE (3 * MAT_ELEMS)
#define GEMM16_SMEM (2 * MAT3_STAGE * 2)       // 61440 -> 2 CTAs/SM

__global__ __launch_bounds__(256, 2)
void gemm_fp16x2(const __half* __restrict__ Ah, const __half* __restrict__ Al,
                 const __half* __restrict__ Bf,
                 float* __restrict__ C, int ldc)
{
    extern __shared__ __half sm16[];

    const int tid  = threadIdx.x;
    const int lane = tid & 31;
    const int wid  = tid >> 5;
    const int wm   = wid & 3;
    const int wn   = wid >> 2;
    const int m0   = blockIdx.y * 128;
    const int n0   = blockIdx.x * 128;

    const __half* srcs[3] = {
        Ah + (size_t)m0 * 1024, Al + (size_t)m0 * 1024, Bf + (size_t)n0 * 1024 };

    const unsigned smb = (unsigned)__cvta_generic_to_shared(sm16);

    auto stage = [&](int kb, int buf) {
        const unsigned dbase = smb + (unsigned)buf * MAT3_STAGE * 2;
#pragma unroll
        for (int mat = 0; mat < 3; ++mat) {
            const __half* s = srcs[mat];
            const unsigned mb = dbase + (unsigned)mat * MAT_ELEMS * 2;
#pragma unroll
            for (int j = 0; j < 2; ++j) {
                const int chunk = tid + j * 256;
                const int row   = chunk >> 2;
                const int c8    = (chunk & 3) * 8;
                const __half* sp = s + (size_t)row * 1024 + kb * 32 + c8;
                const unsigned dst = mb + (unsigned)(row * PK + c8) * 2;
                asm volatile("cp.async.cg.shared.global [%0], [%1], 16;\n" :: "r"(dst), "l"(sp));
            }
        }
        asm volatile("cp.async.commit_group;\n" ::: "memory");
    };

    float acc[2][8][4];
#pragma unroll
    for (int i = 0; i < 2; ++i)
#pragma unroll
        for (int j = 0; j < 8; ++j)
#pragma unroll
            for (int t = 0; t < 4; ++t) acc[i][j][t] = 0.f;

    const unsigned aOff = (unsigned)((wm * 32 + (lane & 15)) * PK + (lane >> 4) * 8) * 2;
    const unsigned bOff = (unsigned)((wn * 64 + (lane & 15)) * PK + (lane >> 4) * 8) * 2;

    stage(0, 0);

    const int KB = 1024 / 32;
    for (int kb = 0; kb < KB; ++kb) {
        const int cur = kb & 1;
        if (kb + 1 < KB) {
            stage(kb + 1, cur ^ 1);
            asm volatile("cp.async.wait_group 1;\n" ::: "memory");
        } else {
            asm volatile("cp.async.wait_group 0;\n" ::: "memory");
        }
        __syncthreads();

        const unsigned base = smb + (unsigned)cur * MAT3_STAGE * 2;
        const unsigned bAh = base;
        const unsigned bAl = base + MAT_ELEMS * 2;
        const unsigned bBf = base + 2 * MAT_ELEMS * 2;

#pragma unroll
        for (int kc = 0; kc < 2; ++kc) {
            const unsigned ko = (unsigned)(kc * 16) * 2;
            unsigned ah[2][4], al[2][4], bf4[4][4];
#pragma unroll
            for (int mt = 0; mt < 2; ++mt) {
                const unsigned o = aOff + (unsigned)(mt * 16 * PK) * 2 + ko;
                ldsm_x4(ah[mt], bAh + o);
                ldsm_x4(al[mt], bAl + o);
            }
#pragma unroll
            for (int nb = 0; nb < 4; ++nb) {
                const unsigned o = bOff + (unsigned)(nb * 16 * PK) * 2 + ko;
                ldsm_x4(bf4[nb], bBf + o);
            }
#pragma unroll
            for (int mt = 0; mt < 2; ++mt)
#pragma unroll
                for (int nb = 0; nb < 4; ++nb) {
                    unsigned b0[2] = { bf4[nb][0], bf4[nb][2] };
                    unsigned b1[2] = { bf4[nb][1], bf4[nb][3] };
                    mma_f16r(acc[mt][2 * nb],     ah[mt], b0);
                    mma_f16r(acc[mt][2 * nb + 1], ah[mt], b1);
                }
#pragma unroll
            for (int mt = 0; mt < 2; ++mt)
#pragma unroll
                for (int nb = 0; nb < 4; ++nb) {
                    unsigned b0[2] = { bf4[nb][0], bf4[nb][2] };
                    unsigned b1[2] = { bf4[nb][1], bf4[nb][3] };
                    mma_f16r(acc[mt][2 * nb],     al[mt], b0);
                    mma_f16r(acc[mt][2 * nb + 1], al[mt], b1);
                }
        }
        __syncthreads();
    }

    const int crow0 = m0 + wm * 32 + (lane >> 2);
    const int ccol0 = n0 + wn * 64 + (lane & 3) * 2;
#pragma unroll
    for (int mt = 0; mt < 2; ++mt)
#pragma unroll
        for (int nt = 0; nt < 8; ++nt) {
            float* p0 = C + (size_t)(crow0 + mt * 16) * ldc + ccol0 + nt * 8;
            float* p1 = p0 + 8 * ldc;
            *(float2*)p0 = make_float2(acc[mt][nt][0], acc[mt][nt][1]);
            *(float2*)p1 = make_float2(acc[mt][nt][2], acc[mt][nt][3]);
        }
}

// ---------------- RMSNorm + 2D RoPE epilogue (V -> fp16 transposed) ----------------
__global__ __launch_bounds__(256)
void qkv_epilogue(const float* __restrict__ qkv,
                  const float* __restrict__ qg, const float* __restrict__ kg,
                  const int* __restrict__ pos,
                  float* __restrict__ q, float* __restrict__ k, __half* __restrict__ vt)
{
    const int w     = (blockIdx.x * blockDim.x + threadIdx.x) >> 5;
    const int lane  = threadIdx.x & 31;
    const int token = w >> 5;
    const int row   = w & 31;
    const int b     = token >> 10;
    const int s     = token & 1023;

    const float* src;
    float* dst = nullptr;
    __half* vdst = nullptr;
    const float* gamma = nullptr;
    bool rope = true;
    if (row < 16) {
        src = qkv + (size_t)token * 2048 + row * 64;
        dst = q + ((size_t)(b * NH + row) * SS_ + s) * HD;
        gamma = qg;
    } else if (row < 24) {
        const int h = row - 16;
        src = qkv + (size_t)token * 2048 + 1024 + h * 64;
        dst = k + ((size_t)(b * NKH + h) * SS_ + s) * HD;
        gamma = kg;
    } else {
        const int h = row - 24;
        src = qkv + (size_t)token * 2048 + 1536 + h * 64;
        vdst = vt + ((size_t)(b * NKH + h) * HD) * SS_ + s;
        rope = false;
    }

    float x0 = src[lane];
    float x1 = src[lane + 32];
    float ssum = x0 * x0 + x1 * x1;
#pragma unroll
    for (int off = 16; off; off >>= 1)
        ssum += __shfl_xor_sync(0xffffffffu, ssum, off);
    const float r = rsqrtf(ssum * (1.0f / 64.0f) + 1e-6f);
    x0 *= r; x1 *= r;
    if (gamma) {
        x0 *= 1.0f + gamma[lane];
        x1 *= 1.0f + gamma[lane + 32];
    }
    if (rope) {
        const float px = (float)pos[token * 2 + 0];
        const float py = (float)pos[token * 2 + 1];
        const int j = lane & 15;
        const float invf = exp2f(-13.2877123795494f * (float)j * (1.0f / 16.0f));
        float s0, c0, s1, c1;
        sincosf(px * invf, &s0, &c0);
        sincosf(py * invf, &s1, &c1);
        const float p0 = __shfl_xor_sync(0xffffffffu, x0, 16);
        const float p1 = __shfl_xor_sync(0xffffffffu, x1, 16);
        if (lane < 16) { x0 = x0 * c0 - p0 * s0; x1 = x1 * c1 - p1 * s1; }
        else           { x0 = x0 * c0 + p0 * s0; x1 = x1 * c1 + p1 * s1; }
        dst[lane]      = x0;
        dst[lane + 32] = x1;
    } else {
        vdst[(size_t)lane * SS_]        = __float2half_rn(x0);
        vdst[(size_t)(lane + 32) * SS_] = __float2half_rn(x1);
    }
}

// ================= flash attention: occ-2 cap + low-register QK loop =================
__device__ __forceinline__ void fsplit_bf16(float x, float y, unsigned& hi, unsigned& lo)
{
    __nv_bfloat162 h = __floats2bfloat162_rn(x, y);
    hi = *(unsigned*)&h;
    __nv_bfloat162 l = __floats2bfloat162_rn(x - __bfloat162float(h.x), y - __bfloat162float(h.y));
    lo = *(unsigned*)&l;
}

__global__ __launch_bounds__(256, 2)
void flash_attn_mma(const float* __restrict__ gq, const float* __restrict__ gk,
                    const __half* __restrict__ gvt, float* __restrict__ ao)
{
    const int lane = threadIdx.x & 31;
    const int w    = threadIdx.x >> 5;
    const int bh   = blockIdx.y;
    const int b    = bh >> 4;
    const int h    = bh & 15;
    const int kh   = h >> 1;
    const int q0   = blockIdx.x * 128 + w * 16;

    const int r  = lane >> 2;
    const int cq = (lane & 3) * 2;

    const float* qb = gq  + ((size_t)(b * NH  + h ) * SS_ + q0) * HD;
    const float* kb = gk  + ((size_t)(b * NKH + kh) * SS_) * HD;
    const __half* vt = gvt + ((size_t)(b * NKH + kh) * HD) * SS_;

    unsigned qh[4][4], ql[4][4];
#pragma unroll
    for (int kc = 0; kc < 4; ++kc)
#pragma unroll
        for (int i = 0; i < 4; ++i) {
            const int row = r + (i & 1) * 8;
            const int col = kc * 16 + cq + (i & 2) * 4;
            float2 t = *(const float2*)(qb + (size_t)row * HD + col);
            fsplit_bf16(t.x, t.y, qh[kc][i], ql[kc][i]);
        }

    float o[8][4];
#pragma unroll
    for (int nt = 0; nt < 8; ++nt)
#pragma unroll
        for (int j = 0; j < 4; ++j) o[nt][j] = 0.f;
    float m0 = -1e30f, m1 = -1e30f, l0 = 0.f, l1 = 0.f;

    for (int kt = 0; kt < 16; ++kt) {
        const float* kp = kb + (size_t)kt * 64 * HD;

        float s[8][4];
#pragma unroll
        for (int nt = 0; nt < 8; ++nt)
#pragma unroll
            for (int j = 0; j < 4; ++j) s[nt][j] = 0.f;

        // QK: per-nt load+mma to keep K-fragment live range minimal (4 regs).
        // Per-accumulator order stays hh, hl, lh -> bit-identical results.
#pragma unroll
        for (int kc = 0; kc < 4; ++kc) {
#pragma unroll
            for (int nt = 0; nt < 8; ++nt) {
                const float* rowp = kp + (size_t)(nt * 8 + r) * HD + kc * 16 + cq;
                float2 t0 = *(const float2*)rowp;
                float2 t1 = *(const float2*)(rowp + 8);
                unsigned kfh2[2], kfl2[2];
                fsplit_bf16(t0.x, t0.y, kfh2[0], kfl2[0]);
                fsplit_bf16(t1.x, t1.y, kfh2[1], kfl2[1]);
                mma_bf16(s[nt], qh[kc], kfh2);
                mma_bf16(s[nt], qh[kc], kfl2);
                mma_bf16(s[nt], ql[kc], kfh2);
            }
        }

        float mx0 = s[0][0], mx1 = s[0][2];
#pragma unroll
        for (int nt = 0; nt < 8; ++nt) {
            mx0 = fmaxf(mx0, fmaxf(s[nt][0], s[nt][1]));
            mx1 = fmaxf(mx1, fmaxf(s[nt][2], s[nt][3]));
        }
        mx0 = fmaxf(mx0, __shfl_xor_sync(0xffffffffu, mx0, 1));
        mx0 = fmaxf(mx0, __shfl_xor_sync(0xffffffffu, mx0, 2));
        mx1 = fmaxf(mx1, __shfl_xor_sync(0xffffffffu, mx1, 1));
        mx1 = fmaxf(mx1, __shfl_xor_sync(0xffffffffu, mx1, 2));

        const float mn0 = fmaxf(m0, mx0);
        const float mn1 = fmaxf(m1, mx1);
        const float al0 = __expf(m0 - mn0);
        const float al1 = __expf(m1 - mn1);
        m0 = mn0; m1 = mn1;

        float rs0 = 0.f, rs1 = 0.f;
#pragma unroll
        for (int nt = 0; nt < 8; ++nt) {
            s[nt][0] = __expf(s[nt][0] - mn0);
            s[nt][1] = __expf(s[nt][1] - mn0);
            s[nt][2] = __expf(s[nt][2] - mn1);
            s[nt][3] = __expf(s[nt][3] - mn1);
            rs0 += s[nt][0] + s[nt][1];
            rs1 += s[nt][2] + s[nt][3];
        }
        rs0 += __shfl_xor_sync(0xffffffffu, rs0, 1);
        rs0 += __shfl_xor_sync(0xffffffffu, rs0, 2);
        rs1 += __shfl_xor_sync(0xffffffffu, rs1, 1);
        rs1 += __shfl_xor_sync(0xffffffffu, rs1, 2);
        l0 = l0 * al0 + rs0;
        l1 = l1 * al1 + rs1;

#pragma unroll
        for (int nt = 0; nt < 8; ++nt) {
            o[nt][0] *= al0; o[nt][1] *= al0;
            o[nt][2] *= al1; o[nt][3] *= al1;
        }

#pragma unroll
        for (int kc = 0; kc < 4; ++kc) {
            unsigned pa[4];
            {
                __half2 t;
                t = __floats2half2_rn(s[2 * kc][0],     s[2 * kc][1]);     pa[0] = *(unsigned*)&t;
                t = __floats2half2_rn(s[2 * kc][2],     s[2 * kc][3]);     pa[1] = *(unsigned*)&t;
                t = __floats2half2_rn(s[2 * kc + 1][0], s[2 * kc + 1][1]); pa[2] = *(unsigned*)&t;
                t = __floats2half2_rn(s[2 * kc + 1][2], s[2 * kc + 1][3]); pa[3] = *(unsigned*)&t;
            }
#pragma unroll
            for (int ntd = 0; ntd < 8; ++ntd) {
                const size_t off = (size_t)(ntd * 8 + r) * SS_ + kt * 64 + kc * 16 + cq;
                unsigned vh2[2];
                vh2[0] = *(const unsigned*)(vt + off);
                vh2[1] = *(const unsigned*)(vt + off + 8);
                mma_f16r(o[ntd], pa, vh2);
            }
        }
    }

    const float inv0 = 1.0f / l0;
    const float inv1 = 1.0f / l1;
    const int sg0 = q0 + r;
    const int sg1 = q0 + r + 8;
    float* a0 = ao + (((size_t)b * SS_ + sg0) * NH + h) * HD;
    float* a1 = ao + (((size_t)b * SS_ + sg1) * NH + h) * HD;
#pragma unroll
    for (int ntd = 0; ntd < 8; ++ntd) {
        *(float2*)(a0 + ntd * 8 + cq) = make_float2(o[ntd][0] * inv0, o[ntd][1] * inv0);
        *(float2*)(a1 + ntd * 8 + cq) = make_float2(o[ntd][2] * inv1, o[ntd][3] * inv1);
    }
}

// ---------------- launch ----------------
extern "C" void kernel_launch(void* const* d_in, const int* in_sizes, int n_in,
                              void* d_out, int out_size)
{
    (void)in_sizes; (void)n_in; (void)out_size;
    const float* hidden = (const float*)d_in[0];
    const float* Wq     = (const float*)d_in[1];
    const float* Wk     = (const float*)d_in[2];
    const float* Wv     = (const float*)d_in[3];
    const float* Wo     = (const float*)d_in[4];
    const float* qg     = (const float*)d_in[5];
    const float* kg     = (const float*)d_in[6];
    const int*   pos    = (const int*)d_in[7];
    float* out = (float*)d_out;

    float *qkv, *q, *k, *ao;
    __nv_bfloat16 *ah, *al, *wth, *wtl;
    __half *wof, *aofh, *aofl, *vth;
    cudaGetSymbolAddress((void**)&qkv,  g_qkv);
    cudaGetSymbolAddress((void**)&q,    g_q);
    cudaGetSymbolAddress((void**)&k,    g_k);
    cudaGetSymbolAddress((void**)&ao,   g_ao);
    cudaGetSymbolAddress((void**)&ah,   g_ah);
    cudaGetSymbolAddress((void**)&al,   g_al);
    cudaGetSymbolAddress((void**)&wth,  g_wth);
    cudaGetSymbolAddress((void**)&wtl,  g_wtl);
    cudaGetSymbolAddress((void**)&wof,  g_wof);
    cudaGetSymbolAddress((void**)&aofh, g_aofh);
    cudaGetSymbolAddress((void**)&aofl, g_aofl);
    cudaGetSymbolAddress((void**)&vth,  g_vth);

    cudaFuncSetAttribute(gemm_presplit, cudaFuncAttributeMaxDynamicSharedMemorySize, GEMM_SMEM);
    cudaFuncSetAttribute(gemm_fp16x2,   cudaFuncAttributeMaxDynamicSharedMemorySize, GEMM16_SMEM);

    const dim3 blk(256);

    // 1: hidden split
    convert_split<<<TOKENS * 1024 / 4 / 256, blk>>>(hidden, ah, al, TOKENS * 1024 / 4);
    // 2: Wo fp16 transpose
    transpose_f16<<<dim3(32, 32), blk>>>(Wo, wof, 1024);
    // 3: merged Wq/Wk/Wv transpose-split
    transpose_split3<<<dim3(64, 32), blk>>>(Wq, Wk, Wv, wth, wtl);
    // 4: fused QKV GEMM (ncu capture position)
    gemm_presplit<<<dim3(16, 32), blk, GEMM_SMEM>>>(ah, al, wth, wtl, qkv, 2048);
    // 5: RMSNorm + RoPE; V -> fp16 transposed
    qkv_epilogue<<<TOKENS * 32 / 8, blk>>>(qkv, qg, kg, pos, q, k, vth);
    // 6: attention (occ-2 cap, low-register QK loop)
    flash_attn_mma<<<dim3(SS_ / 128, BB * NH), blk>>>(q, k, vth, ao);
    // 7: AO fp16 split
    convert_split_f16<<<TOKENS * 1024 / 4 / 256, blk>>>(ao, aofh, aofl, TOKENS * 1024 / 4);
    // 8: O projection
    gemm_fp16x2<<<dim3(8, 32), blk, GEMM16_SMEM>>>(aofh, aofl, wof, out, 1024);
}

// round 17
// speedup vs baseline: 1.5340x; 1.3781x over previous
#include <cuda_runtime.h>
#include <cuda_bf16.h>
#include <cuda_fp16.h>
#include <math.h>
#include <stdint.h>

#define BB   4
#define SS_  1024
#define HIDD 1024
#define NH   16
#define NKH  8
#define HD   64
#define TOKENS (BB * SS_)   // 4096

// ---------------- scratch (no allocations allowed) ----------------
__device__ float g_qkv[(size_t)TOKENS * 2048];
__device__ float g_q[(size_t)BB * NH  * SS_ * HD];
__device__ float g_ao[(size_t)TOKENS * NH * HD];

__device__ __align__(256) __nv_bfloat16 g_ah [(size_t)TOKENS * 1024];
__device__ __align__(256) __nv_bfloat16 g_al [(size_t)TOKENS * 1024];
__device__ __align__(256) __nv_bfloat16 g_wth[(size_t)2048 * 1024];
__device__ __align__(256) __nv_bfloat16 g_wtl[(size_t)2048 * 1024];
__device__ __align__(256) __half        g_wof[(size_t)1024 * 1024];
__device__ __align__(256) __half        g_aofh[(size_t)TOKENS * 1024];
__device__ __align__(256) __half        g_aofl[(size_t)TOKENS * 1024];
__device__ __align__(256) __half        g_vth[(size_t)BB * NKH * HD * SS_];   // V^T fp16 [b][kh][d][s]
__device__ __align__(256) __nv_bfloat16 g_kh [(size_t)BB * NKH * SS_ * HD];   // K hi bf16 [b][kh][s][d]
__device__ __align__(256) __nv_bfloat16 g_kl [(size_t)BB * NKH * SS_ * HD];   // K lo bf16

// ================= mma / ldmatrix helpers =================
__device__ __forceinline__ void mma_bf16(float* d, const unsigned* a, const unsigned* b)
{
    asm volatile(
        "mma.sync.aligned.m16n8k16.row.col.f32.bf16.bf16.f32 "
        "{%0,%1,%2,%3}, {%4,%5,%6,%7}, {%8,%9}, {%0,%1,%2,%3};\n"
        : "+f"(d[0]), "+f"(d[1]), "+f"(d[2]), "+f"(d[3])
        : "r"(a[0]), "r"(a[1]), "r"(a[2]), "r"(a[3]), "r"(b[0]), "r"(b[1]));
}
__device__ __forceinline__ void mma_f16r(float* d, const unsigned* a, const unsigned* b)
{
    asm volatile(
        "mma.sync.aligned.m16n8k16.row.col.f32.f16.f16.f32 "
        "{%0,%1,%2,%3}, {%4,%5,%6,%7}, {%8,%9}, {%0,%1,%2,%3};\n"
        : "+f"(d[0]), "+f"(d[1]), "+f"(d[2]), "+f"(d[3])
        : "r"(a[0]), "r"(a[1]), "r"(a[2]), "r"(a[3]), "r"(b[0]), "r"(b[1]));
}
__device__ __forceinline__ void ldsm_x4(unsigned* r, unsigned addr)
{
    asm volatile("ldmatrix.sync.aligned.m8n8.x4.shared.b16 {%0,%1,%2,%3}, [%4];\n"
                 : "=r"(r[0]), "=r"(r[1]), "=r"(r[2]), "=r"(r[3]) : "r"(addr));
}

// ================= converts =================
__global__ __launch_bounds__(256)
void convert_split(const float* __restrict__ X, __nv_bfloat16* __restrict__ H,
                   __nv_bfloat16* __restrict__ L, int n4)
{
    const int i = blockIdx.x * 256 + threadIdx.x;
    if (i >= n4) return;
    float4 v = ((const float4*)X)[i];
    __nv_bfloat162 h0 = __floats2bfloat162_rn(v.x, v.y);
    __nv_bfloat162 h1 = __floats2bfloat162_rn(v.z, v.w);
    __nv_bfloat162 l0 = __floats2bfloat162_rn(v.x - __bfloat162float(h0.x), v.y - __bfloat162float(h0.y));
    __nv_bfloat162 l1 = __floats2bfloat162_rn(v.z - __bfloat162float(h1.x), v.w - __bfloat162float(h1.y));
    *(__nv_bfloat162*)&H[(size_t)4 * i]     = h0;
    *(__nv_bfloat162*)&H[(size_t)4 * i + 2] = h1;
    *(__nv_bfloat162*)&L[(size_t)4 * i]     = l0;
    *(__nv_bfloat162*)&L[(size_t)4 * i + 2] = l1;
}

__global__ __launch_bounds__(256)
void convert_split_f16(const float* __restrict__ X, __half* __restrict__ H,
                       __half* __restrict__ L, int n4)
{
    const int i = blockIdx.x * 256 + threadIdx.x;
    if (i >= n4) return;
    float4 v = ((const float4*)X)[i];
    __half2 h0 = __floats2half2_rn(v.x, v.y);
    __half2 h1 = __floats2half2_rn(v.z, v.w);
    __half2 l0 = __floats2half2_rn(v.x - __half2float(__low2half(h0)), v.y - __half2float(__high2half(h0)));
    __half2 l1 = __floats2half2_rn(v.z - __half2float(__low2half(h1)), v.w - __half2float(__high2half(h1)));
    *(__half2*)&H[(size_t)4 * i]     = h0;
    *(__half2*)&H[(size_t)4 * i + 2] = h1;
    *(__half2*)&L[(size_t)4 * i]     = l0;
    *(__half2*)&L[(size_t)4 * i + 2] = l1;
}

// Merged weight transpose: Wq/Wk/Wv -> wth/wtl [n][1024 k] bf16 split, one launch.
__global__ __launch_bounds__(256)
void transpose_split3(const float* __restrict__ Wq, const float* __restrict__ Wk,
                      const float* __restrict__ Wv,
                      __nv_bfloat16* __restrict__ TH, __nv_bfloat16* __restrict__ TL)
{
    __shared__ float t[32][33];
    const int tx = threadIdx.x & 31;
    const int ty = threadIdx.x >> 5;
    const int xb = blockIdx.x;           // 0..63
    const int k0 = blockIdx.y * 32;

    const float* W;
    int N, n0;
    size_t obase;
    if (xb < 32)      { W = Wq; N = 1024; n0 = xb * 32;        obase = 0; }
    else if (xb < 48) { W = Wk; N = 512;  n0 = (xb - 32) * 32; obase = (size_t)1024 * 1024; }
    else              { W = Wv; N = 512;  n0 = (xb - 48) * 32; obase = (size_t)1536 * 1024; }

#pragma unroll
    for (int j = 0; j < 4; ++j)
        t[ty + 8 * j][tx] = W[(size_t)(k0 + ty + 8 * j) * N + n0 + tx];
    __syncthreads();
#pragma unroll
    for (int j = 0; j < 4; ++j) {
        const int n = ty + 8 * j;
        const float v = t[tx][n];
        const __nv_bfloat16 h = __float2bfloat16(v);
        TH[obase + (size_t)(n0 + n) * 1024 + k0 + tx] = h;
        TL[obase + (size_t)(n0 + n) * 1024 + k0 + tx] = __float2bfloat16(v - __bfloat162float(h));
    }
}

// Wo [1024 k][1024 n] fp32 -> T [n][1024 k] fp16 single
__global__ __launch_bounds__(256)
void transpose_f16(const float* __restrict__ W, __half* __restrict__ T, int N)
{
    __shared__ float t[32][33];
    const int tx = threadIdx.x & 31;
    const int ty = threadIdx.x >> 5;
    const int n0 = blockIdx.x * 32, k0 = blockIdx.y * 32;
#pragma unroll
    for (int j = 0; j < 4; ++j)
        t[ty + 8 * j][tx] = W[(size_t)(k0 + ty + 8 * j) * N + n0 + tx];
    __syncthreads();
#pragma unroll
    for (int j = 0; j < 4; ++j) {
        const int n = ty + 8 * j;
        T[(size_t)(n0 + n) * 1024 + k0 + tx] = __float2half_rn(t[tx][n]);
    }
}

// ================= bf16 3-pass GEMM, 2-stage pipeline, 2 CTAs/SM (R16) =================
#define PK 40
#define MAT_ELEMS (128 * PK)
#define STAGE_ELEMS (4 * MAT_ELEMS)
#define GEMM_SMEM (2 * STAGE_ELEMS * 2)        // 81920

__global__ __launch_bounds__(256, 2)
void gemm_presplit(const __nv_bfloat16* __restrict__ Ah, const __nv_bfloat16* __restrict__ Al,
                   const __nv_bfloat16* __restrict__ Bh, const __nv_bfloat16* __restrict__ Bl,
                   float* __restrict__ C, int ldc)
{
    extern __shared__ __nv_bfloat16 sm[];

    const int tid  = threadIdx.x;
    const int lane = tid & 31;
    const int wid  = tid >> 5;
    const int wm   = wid & 3;
    const int wn   = wid >> 2;
    const int m0   = blockIdx.y * 128;
    const int n0   = blockIdx.x * 128;

    const __nv_bfloat16* srcs[4] = {
        Ah + (size_t)m0 * 1024, Al + (size_t)m0 * 1024,
        Bh + (size_t)n0 * 1024, Bl + (size_t)n0 * 1024 };

    const unsigned smb = (unsigned)__cvta_generic_to_shared(sm);

    auto stage = [&](int kb, int buf) {
        const unsigned dbase = smb + (unsigned)buf * STAGE_ELEMS * 2;
#pragma unroll
        for (int mat = 0; mat < 4; ++mat) {
            const __nv_bfloat16* s = srcs[mat];
            const unsigned mb = dbase + (unsigned)mat * MAT_ELEMS * 2;
#pragma unroll
            for (int j = 0; j < 2; ++j) {
                const int chunk = tid + j * 256;
                const int row   = chunk >> 2;
                const int c8    = (chunk & 3) * 8;
                const __nv_bfloat16* sp = s + (size_t)row * 1024 + kb * 32 + c8;
                const unsigned dst = mb + (unsigned)(row * PK + c8) * 2;
                asm volatile("cp.async.cg.shared.global [%0], [%1], 16;\n" :: "r"(dst), "l"(sp));
            }
        }
        asm volatile("cp.async.commit_group;\n" ::: "memory");
    };

    float acc[2][8][4];
#pragma unroll
    for (int i = 0; i < 2; ++i)
#pragma unroll
        for (int j = 0; j < 8; ++j)
#pragma unroll
            for (int t = 0; t < 4; ++t) acc[i][j][t] = 0.f;

    const unsigned aOff = (unsigned)((wm * 32 + (lane & 15)) * PK + (lane >> 4) * 8) * 2;
    const unsigned bOff = (unsigned)((wn * 64 + (lane & 15)) * PK + (lane >> 4) * 8) * 2;

    stage(0, 0);

    const int KB = 1024 / 32;
    for (int kb = 0; kb < KB; ++kb) {
        const int cur = kb & 1;
        if (kb + 1 < KB) {
            stage(kb + 1, cur ^ 1);
            asm volatile("cp.async.wait_group 1;\n" ::: "memory");
        } else {
            asm volatile("cp.async.wait_group 0;\n" ::: "memory");
        }
        __syncthreads();

        const unsigned base = smb + (unsigned)cur * STAGE_ELEMS * 2;
        const unsigned bAh = base;
        const unsigned bAl = base + MAT_ELEMS * 2;
        const unsigned bBh = base + 2 * MAT_ELEMS * 2;
        const unsigned bBl = base + 3 * MAT_ELEMS * 2;

#pragma unroll
        for (int kc = 0; kc < 2; ++kc) {
            const unsigned ko = (unsigned)(kc * 16) * 2;
            unsigned ah[2][4], al[2][4], bh[4][4], bl[4][4];
#pragma unroll
            for (int mt = 0; mt < 2; ++mt) {
                const unsigned o = aOff + (unsigned)(mt * 16 * PK) * 2 + ko;
                ldsm_x4(ah[mt], bAh + o);
                ldsm_x4(al[mt], bAl + o);
            }
#pragma unroll
            for (int nb = 0; nb < 4; ++nb) {
                const unsigned o = bOff + (unsigned)(nb * 16 * PK) * 2 + ko;
                ldsm_x4(bh[nb], bBh + o);
                ldsm_x4(bl[nb], bBl + o);
            }
#pragma unroll
            for (int mt = 0; mt < 2; ++mt)
#pragma unroll
                for (int nb = 0; nb < 4; ++nb) {
                    unsigned b0h[2] = { bh[nb][0], bh[nb][2] };
                    unsigned b1h[2] = { bh[nb][1], bh[nb][3] };
                    mma_bf16(acc[mt][2 * nb],     ah[mt], b0h);
                    mma_bf16(acc[mt][2 * nb + 1], ah[mt], b1h);
                }
#pragma unroll
            for (int mt = 0; mt < 2; ++mt)
#pragma unroll
                for (int nb = 0; nb < 4; ++nb) {
                    unsigned b0l[2] = { bl[nb][0], bl[nb][2] };
                    unsigned b1l[2] = { bl[nb][1], bl[nb][3] };
                    mma_bf16(acc[mt][2 * nb],     ah[mt], b0l);
                    mma_bf16(acc[mt][2 * nb + 1], ah[mt], b1l);
                }
#pragma unroll
            for (int mt = 0; mt < 2; ++mt)
#pragma unroll
                for (int nb = 0; nb < 4; ++nb) {
                    unsigned b0h[2] = { bh[nb][0], bh[nb][2] };
                    unsigned b1h[2] = { bh[nb][1], bh[nb][3] };
                    mma_bf16(acc[mt][2 * nb],     al[mt], b0h);
                    mma_bf16(acc[mt][2 * nb + 1], al[mt], b1h);
                }
        }
        __syncthreads();
    }

    const int crow0 = m0 + wm * 32 + (lane >> 2);
    const int ccol0 = n0 + wn * 64 + (lane & 3) * 2;
#pragma unroll
    for (int mt = 0; mt < 2; ++mt)
#pragma unroll
        for (int nt = 0; nt < 8; ++nt) {
            float* p0 = C + (size_t)(crow0 + mt * 16) * ldc + ccol0 + nt * 8;
            float* p1 = p0 + 8 * ldc;
            *(float2*)p0 = make_float2(acc[mt][nt][0], acc[mt][nt][1]);
            *(float2*)p1 = make_float2(acc[mt][nt][2], acc[mt][nt][3]);
        }
}

// ================= fp16 2-pass GEMM, 2-stage pipeline, 2 CTAs/SM (R16) =================
#define MAT3_STAGE (3 * MAT_ELEMS)
#define GEMM16_SMEM (2 * MAT3_STAGE * 2)       // 61440

__global__ __launch_bounds__(256, 2)
void gemm_fp16x2(const __half* __restrict__ Ah, const __half* __restrict__ Al,
                 const __half* __restrict__ Bf,
                 float* __restrict__ C, int ldc)
{
    extern __shared__ __half sm16[];

    const int tid  = threadIdx.x;
    const int lane = tid & 31;
    const int wid  = tid >> 5;
    const int wm   = wid & 3;
    const int wn   = wid >> 2;
    const int m0   = blockIdx.y * 128;
    const int n0   = blockIdx.x * 128;

    const __half* srcs[3] = {
        Ah + (size_t)m0 * 1024, Al + (size_t)m0 * 1024, Bf + (size_t)n0 * 1024 };

    const unsigned smb = (unsigned)__cvta_generic_to_shared(sm16);

    auto stage = [&](int kb, int buf) {
        const unsigned dbase = smb + (unsigned)buf * MAT3_STAGE * 2;
#pragma unroll
        for (int mat = 0; mat < 3; ++mat) {
            const __half* s = srcs[mat];
            const unsigned mb = dbase + (unsigned)mat * MAT_ELEMS * 2;
#pragma unroll
            for (int j = 0; j < 2; ++j) {
                const int chunk = tid + j * 256;
                const int row   = chunk >> 2;
                const int c8    = (chunk & 3) * 8;
                const __half* sp = s + (size_t)row * 1024 + kb * 32 + c8;
                const unsigned dst = mb + (unsigned)(row * PK + c8) * 2;
                asm volatile("cp.async.cg.shared.global [%0], [%1], 16;\n" :: "r"(dst), "l"(sp));
            }
        }
        asm volatile("cp.async.commit_group;\n" ::: "memory");
    };

    float acc[2][8][4];
#pragma unroll
    for (int i = 0; i < 2; ++i)
#pragma unroll
        for (int j = 0; j < 8; ++j)
#pragma unroll
            for (int t = 0; t < 4; ++t) acc[i][j][t] = 0.f;

    const unsigned aOff = (unsigned)((wm * 32 + (lane & 15)) * PK + (lane >> 4) * 8) * 2;
    const unsigned bOff = (unsigned)((wn * 64 + (lane & 15)) * PK + (lane >> 4) * 8) * 2;

    stage(0, 0);

    const int KB = 1024 / 32;
    for (int kb = 0; kb < KB; ++kb) {
        const int cur = kb & 1;
        if (kb + 1 < KB) {
            stage(kb + 1, cur ^ 1);
            asm volatile("cp.async.wait_group 1;\n" ::: "memory");
        } else {
            asm volatile("cp.async.wait_group 0;\n" ::: "memory");
        }
        __syncthreads();

        const unsigned base = smb + (unsigned)cur * MAT3_STAGE * 2;
        const unsigned bAh = base;
        const unsigned bAl = base + MAT_ELEMS * 2;
        const unsigned bBf = base + 2 * MAT_ELEMS * 2;

#pragma unroll
        for (int kc = 0; kc < 2; ++kc) {
            const unsigned ko = (unsigned)(kc * 16) * 2;
            unsigned ah[2][4], al[2][4], bf4[4][4];
#pragma unroll
            for (int mt = 0; mt < 2; ++mt) {
                const unsigned o = aOff + (unsigned)(mt * 16 * PK) * 2 + ko;
                ldsm_x4(ah[mt], bAh + o);
                ldsm_x4(al[mt], bAl + o);
            }
#pragma unroll
            for (int nb = 0; nb < 4; ++nb) {
                const unsigned o = bOff + (unsigned)(nb * 16 * PK) * 2 + ko;
                ldsm_x4(bf4[nb], bBf + o);
            }
#pragma unroll
            for (int mt = 0; mt < 2; ++mt)
#pragma unroll
                for (int nb = 0; nb < 4; ++nb) {
                    unsigned b0[2] = { bf4[nb][0], bf4[nb][2] };
                    unsigned b1[2] = { bf4[nb][1], bf4[nb][3] };
                    mma_f16r(acc[mt][2 * nb],     ah[mt], b0);
                    mma_f16r(acc[mt][2 * nb + 1], ah[mt], b1);
                }
#pragma unroll
            for (int mt = 0; mt < 2; ++mt)
#pragma unroll
                for (int nb = 0; nb < 4; ++nb) {
                    unsigned b0[2] = { bf4[nb][0], bf4[nb][2] };
                    unsigned b1[2] = { bf4[nb][1], bf4[nb][3] };
                    mma_f16r(acc[mt][2 * nb],     al[mt], b0);
                    mma_f16r(acc[mt][2 * nb + 1], al[mt], b1);
                }
        }
        __syncthreads();
    }

    const int crow0 = m0 + wm * 32 + (lane >> 2);
    const int ccol0 = n0 + wn * 64 + (lane & 3) * 2;
#pragma unroll
    for (int mt = 0; mt < 2; ++mt)
#pragma unroll
        for (int nt = 0; nt < 8; ++nt) {
            float* p0 = C + (size_t)(crow0 + mt * 16) * ldc + ccol0 + nt * 8;
            float* p1 = p0 + 8 * ldc;
            *(float2*)p0 = make_float2(acc[mt][nt][0], acc[mt][nt][1]);
            *(float2*)p1 = make_float2(acc[mt][nt][2], acc[mt][nt][3]);
        }
}

// ---------------- RMSNorm + 2D RoPE epilogue (K -> bf16 hi/lo, V -> fp16 transposed) ----------------
__global__ __launch_bounds__(256)
void qkv_epilogue(const float* __restrict__ qkv,
                  const float* __restrict__ qg, const float* __restrict__ kg,
                  const int* __restrict__ pos,
                  float* __restrict__ q,
                  __nv_bfloat16* __restrict__ kh, __nv_bfloat16* __restrict__ kl,
                  __half* __restrict__ vt)
{
    const int w     = (blockIdx.x * blockDim.x + threadIdx.x) >> 5;
    const int lane  = threadIdx.x & 31;
    const int token = w >> 5;
    const int row   = w & 31;
    const int b     = token >> 10;
    const int s     = token & 1023;

    const float* src;
    float* dst = nullptr;
    size_t ko0 = 0, ko1 = 0;
    __half* vdst = nullptr;
    const float* gamma = nullptr;
    int mode;   // 0 = q, 1 = k, 2 = v
    if (row < 16) {
        src = qkv + (size_t)token * 2048 + row * 64;
        dst = q + ((size_t)(b * NH + row) * SS_ + s) * HD;
        gamma = qg;
        mode = 0;
    } else if (row < 24) {
        const int h = row - 16;
        src = qkv + (size_t)token * 2048 + 1024 + h * 64;
        const size_t base = ((size_t)(b * NKH + h) * SS_ + s) * HD;
        ko0 = base + lane;
        ko1 = base + lane + 32;
        gamma = kg;
        mode = 1;
    } else {
        const int h = row - 24;
        src = qkv + (size_t)token * 2048 + 1536 + h * 64;
        vdst = vt + ((size_t)(b * NKH + h) * HD) * SS_ + s;
        mode = 2;
    }

    float x0 = src[lane];
    float x1 = src[lane + 32];
    float ssum = x0 * x0 + x1 * x1;
#pragma unroll
    for (int off = 16; off; off >>= 1)
        ssum += __shfl_xor_sync(0xffffffffu, ssum, off);
    const float r = rsqrtf(ssum * (1.0f / 64.0f) + 1e-6f);
    x0 *= r; x1 *= r;
    if (gamma) {
        x0 *= 1.0f + gamma[lane];
        x1 *= 1.0f + gamma[lane + 32];
    }
    if (mode != 2) {
        const float px = (float)pos[token * 2 + 0];
        const float py = (float)pos[token * 2 + 1];
        const int j = lane & 15;
        const float invf = exp2f(-13.2877123795494f * (float)j * (1.0f / 16.0f));
        float s0, c0, s1, c1;
        sincosf(px * invf, &s0, &c0);
        sincosf(py * invf, &s1, &c1);
        const float p0 = __shfl_xor_sync(0xffffffffu, x0, 16);
        const float p1 = __shfl_xor_sync(0xffffffffu, x1, 16);
        if (lane < 16) { x0 = x0 * c0 - p0 * s0; x1 = x1 * c1 - p1 * s1; }
        else           { x0 = x0 * c0 + p0 * s0; x1 = x1 * c1 + p1 * s1; }
        if (mode == 0) {
            dst[lane]      = x0;
            dst[lane + 32] = x1;
        } else {
            const __nv_bfloat16 h0 = __float2bfloat16(x0);
            const __nv_bfloat16 h1 = __float2bfloat16(x1);
            kh[ko0] = h0;
            kh[ko1] = h1;
            kl[ko0] = __float2bfloat16(x0 - __bfloat162float(h0));
            kl[ko1] = __float2bfloat16(x1 - __bfloat162float(h1));
        }
    } else {
        vdst[(size_t)lane * SS_]        = __float2half_rn(x0);
        vdst[(size_t)(lane + 32) * SS_] = __float2half_rn(x1);
    }
}

// ================= flash attention: smem-staged K/V (GEMM-style data path) =================
#define APK 72                         // 64 + 8 pad (conflict-free ldsm: bank = 4*row mod 32)
#define ATILE (64 * APK)               // elems per matrix tile
#define ASTAGE (3 * ATILE)             // Kh, Kl, Vt
#define ATTN_SMEM (2 * ASTAGE * 2)     // 55296 bytes -> 2 CTAs/SM

__device__ __forceinline__ void fsplit_bf16(float x, float y, unsigned& hi, unsigned& lo)
{
    __nv_bfloat162 h = __floats2bfloat162_rn(x, y);
    hi = *(unsigned*)&h;
    __nv_bfloat162 l = __floats2bfloat162_rn(x - __bfloat162float(h.x), y - __bfloat162float(h.y));
    lo = *(unsigned*)&l;
}

__global__ __launch_bounds__(256, 2)
void flash_attn_mma(const float* __restrict__ gq,
                    const __nv_bfloat16* __restrict__ gkh, const __nv_bfloat16* __restrict__ gkl,
                    const __half* __restrict__ gvt, float* __restrict__ ao)
{
    extern __shared__ char asmem[];
    const unsigned smb = (unsigned)__cvta_generic_to_shared(asmem);

    const int tid  = threadIdx.x;
    const int lane = tid & 31;
    const int w    = tid >> 5;
    const int bh   = blockIdx.y;
    const int b    = bh >> 4;
    const int h    = bh & 15;
    const int kh_  = h >> 1;
    const int q0   = blockIdx.x * 128 + w * 16;

    const int r  = lane >> 2;
    const int cq = (lane & 3) * 2;

    const float* qb = gq + ((size_t)(b * NH + h) * SS_ + q0) * HD;
    const __nv_bfloat16* khp = gkh + (size_t)(b * NKH + kh_) * SS_ * HD;
    const __nv_bfloat16* klp = gkl + (size_t)(b * NKH + kh_) * SS_ * HD;
    const __half*        vtp = gvt + (size_t)(b * NKH + kh_) * HD * SS_;

    // stage K-tile kt into buffer buf: Kh [64 s][64 d], Kl same, Vt [64 d][64 s]
    auto stage = [&](int kt, int buf) {
        const unsigned dbase = smb + (unsigned)buf * ASTAGE * 2;
#pragma unroll
        for (int j = 0; j < 2; ++j) {
            const int chunk = tid + j * 256;      // 0..511
            const int row   = chunk >> 3;         // 0..63
            const int c8    = (chunk & 7) * 8;    // 0..56
            const unsigned doff = (unsigned)(row * APK + c8) * 2;
            const __nv_bfloat16* s0 = khp + (size_t)(kt * 64 + row) * HD + c8;
            asm volatile("cp.async.cg.shared.global [%0], [%1], 16;\n" :: "r"(dbase + doff), "l"(s0));
            const __nv_bfloat16* s1 = klp + (size_t)(kt * 64 + row) * HD + c8;
            asm volatile("cp.async.cg.shared.global [%0], [%1], 16;\n" :: "r"(dbase + ATILE * 2 + doff), "l"(s1));
            const __half* s2 = vtp + (size_t)row * SS_ + kt * 64 + c8;
            asm volatile("cp.async.cg.shared.global [%0], [%1], 16;\n" :: "r"(dbase + 2 * ATILE * 2 + doff), "l"(s2));
        }
        asm volatile("cp.async.commit_group;\n" ::: "memory");
    };

    // Q fragments (fp32 -> bf16 hi/lo once)
    unsigned qh[4][4], ql[4][4];
#pragma unroll
    for (int kc = 0; kc < 4; ++kc)
#pragma unroll
        for (int i = 0; i < 4; ++i) {
            const int row = r + (i & 1) * 8;
            const int col = kc * 16 + cq + (i & 2) * 4;
            float2 t = *(const float2*)(qb + (size_t)row * HD + col);
            fsplit_bf16(t.x, t.y, qh[kc][i], ql[kc][i]);
        }

    float o[8][4];
#pragma unroll
    for (int nt = 0; nt < 8; ++nt)
#pragma unroll
        for (int j = 0; j < 4; ++j) o[nt][j] = 0.f;
    float m0 = -1e30f, m1 = -1e30f, l0 = 0.f, l1 = 0.f;

    // ldsm address base within a tile: row (lane&15), +8-col select by lane>>4
    const unsigned fOff = (unsigned)((lane & 15) * APK + (lane >> 4) * 8) * 2;

    stage(0, 0);

    for (int kt = 0; kt < 16; ++kt) {
        if (kt + 1 < 16) {
            stage(kt + 1, (kt + 1) & 1);
            asm volatile("cp.async.wait_group 1;\n" ::: "memory");
        } else {
            asm volatile("cp.async.wait_group 0;\n" ::: "memory");
        }
        __syncthreads();

        const unsigned base = smb + (unsigned)(kt & 1) * ASTAGE * 2;
        const unsigned bKh = base;
        const unsigned bKl = base + ATILE * 2;
        const unsigned bVt = base + 2 * ATILE * 2;

        float s[8][4];
#pragma unroll
        for (int nt = 0; nt < 8; ++nt)
#pragma unroll
            for (int j = 0; j < 4; ++j) s[nt][j] = 0.f;

        // ---- S = Q K^T (bf16 3-pass; per-acc order hh, hl, lh) ----
#pragma unroll
        for (int kc = 0; kc < 4; ++kc) {
#pragma unroll
            for (int nt2 = 0; nt2 < 4; ++nt2) {
                const unsigned o_ = fOff + (unsigned)(nt2 * 16 * APK + kc * 16) * 2;
                unsigned fh[4], fl[4];
                ldsm_x4(fh, bKh + o_);
                ldsm_x4(fl, bKl + o_);
                unsigned b0h[2] = { fh[0], fh[2] };
                unsigned b1h[2] = { fh[1], fh[3] };
                unsigned b0l[2] = { fl[0], fl[2] };
                unsigned b1l[2] = { fl[1], fl[3] };
                mma_bf16(s[2 * nt2],     qh[kc], b0h);
                mma_bf16(s[2 * nt2],     qh[kc], b0l);
                mma_bf16(s[2 * nt2],     ql[kc], b0h);
                mma_bf16(s[2 * nt2 + 1], qh[kc], b1h);
                mma_bf16(s[2 * nt2 + 1], qh[kc], b1l);
                mma_bf16(s[2 * nt2 + 1], ql[kc], b1h);
            }
        }

        // ---- online softmax ----
        float mx0 = s[0][0], mx1 = s[0][2];
#pragma unroll
        for (int nt = 0; nt < 8; ++nt) {
            mx0 = fmaxf(mx0, fmaxf(s[nt][0], s[nt][1]));
            mx1 = fmaxf(mx1, fmaxf(s[nt][2], s[nt][3]));
        }
        mx0 = fmaxf(mx0, __shfl_xor_sync(0xffffffffu, mx0, 1));
        mx0 = fmaxf(mx0, __shfl_xor_sync(0xffffffffu, mx0, 2));
        mx1 = fmaxf(mx1, __shfl_xor_sync(0xffffffffu, mx1, 1));
        mx1 = fmaxf(mx1, __shfl_xor_sync(0xffffffffu, mx1, 2));

        const float mn0 = fmaxf(m0, mx0);
        const float mn1 = fmaxf(m1, mx1);
        const float al0 = __expf(m0 - mn0);
        const float al1 = __expf(m1 - mn1);
        m0 = mn0; m1 = mn1;

        float rs0 = 0.f, rs1 = 0.f;
#pragma unroll
        for (int nt = 0; nt < 8; ++nt) {
            s[nt][0] = __expf(s[nt][0] - mn0);
            s[nt][1] = __expf(s[nt][1] - mn0);
            s[nt][2] = __expf(s[nt][2] - mn1);
            s[nt][3] = __expf(s[nt][3] - mn1);
            rs0 += s[nt][0] + s[nt][1];
            rs1 += s[nt][2] + s[nt][3];
        }
        rs0 += __shfl_xor_sync(0xffffffffu, rs0, 1);
        rs0 += __shfl_xor_sync(0xffffffffu, rs0, 2);
        rs1 += __shfl_xor_sync(0xffffffffu, rs1, 1);
        rs1 += __shfl_xor_sync(0xffffffffu, rs1, 2);
        l0 = l0 * al0 + rs0;
        l1 = l1 * al1 + rs1;

#pragma unroll
        for (int nt = 0; nt < 8; ++nt) {
            o[nt][0] *= al0; o[nt][1] *= al0;
            o[nt][2] *= al1; o[nt][3] *= al1;
        }

        // ---- O += P V (fp16 P, fp16 V from smem) ----
#pragma unroll
        for (int kc = 0; kc < 4; ++kc) {
            unsigned pa[4];
            {
                __half2 t;
                t = __floats2half2_rn(s[2 * kc][0],     s[2 * kc][1]);     pa[0] = *(unsigned*)&t;
                t = __floats2half2_rn(s[2 * kc][2],     s[2 * kc][3]);     pa[1] = *(unsigned*)&t;
                t = __floats2half2_rn(s[2 * kc + 1][0], s[2 * kc + 1][1]); pa[2] = *(unsigned*)&t;
                t = __floats2half2_rn(s[2 * kc + 1][2], s[2 * kc + 1][3]); pa[3] = *(unsigned*)&t;
            }
#pragma unroll
            for (int nd2 = 0; nd2 < 4; ++nd2) {
                const unsigned o_ = fOff + (unsigned)(nd2 * 16 * APK + kc * 16) * 2;
                unsigned fv[4];
                ldsm_x4(fv, bVt + o_);
                unsigned v0[2] = { fv[0], fv[2] };
                unsigned v1[2] = { fv[1], fv[3] };
                mma_f16r(o[2 * nd2],     pa, v0);
                mma_f16r(o[2 * nd2 + 1], pa, v1);
            }
        }
        __syncthreads();
    }

    const float inv0 = 1.0f / l0;
    const float inv1 = 1.0f / l1;
    const int sg0 = q0 + r;
    const int sg1 = q0 + r + 8;
    float* a0 = ao + (((size_t)b * SS_ + sg0) * NH + h) * HD;
    float* a1 = ao + (((size_t)b * SS_ + sg1) * NH + h) * HD;
#pragma unroll
    for (int ntd = 0; ntd < 8; ++ntd) {
        *(float2*)(a0 + ntd * 8 + cq) = make_float2(o[ntd][0] * inv0, o[ntd][1] * inv0);
        *(float2*)(a1 + ntd * 8 + cq) = make_float2(o[ntd][2] * inv1, o[ntd][3] * inv1);
    }
}

// ---------------- launch ----------------
extern "C" void kernel_launch(void* const* d_in, const int* in_sizes, int n_in,
                              void* d_out, int out_size)
{
    (void)in_sizes; (void)n_in; (void)out_size;
    const float* hidden = (const float*)d_in[0];
    const float* Wq     = (const float*)d_in[1];
    const float* Wk     = (const float*)d_in[2];
    const float* Wv     = (const float*)d_in[3];
    const float* Wo     = (const float*)d_in[4];
    const float* qg     = (const float*)d_in[5];
    const float* kg     = (const float*)d_in[6];
    const int*   pos    = (const int*)d_in[7];
    float* out = (float*)d_out;

    float *qkv, *q, *ao;
    __nv_bfloat16 *ah, *al, *wth, *wtl, *kh, *kl;
    __half *wof, *aofh, *aofl, *vth;
    cudaGetSymbolAddress((void**)&qkv,  g_qkv);
    cudaGetSymbolAddress((void**)&q,    g_q);
    cudaGetSymbolAddress((void**)&ao,   g_ao);
    cudaGetSymbolAddress((void**)&ah,   g_ah);
    cudaGetSymbolAddress((void**)&al,   g_al);
    cudaGetSymbolAddress((void**)&wth,  g_wth);
    cudaGetSymbolAddress((void**)&wtl,  g_wtl);
    cudaGetSymbolAddress((void**)&wof,  g_wof);
    cudaGetSymbolAddress((void**)&aofh, g_aofh);
    cudaGetSymbolAddress((void**)&aofl, g_aofl);
    cudaGetSymbolAddress((void**)&vth,  g_vth);
    cudaGetSymbolAddress((void**)&kh,   g_kh);
    cudaGetSymbolAddress((void**)&kl,   g_kl);

    cudaFuncSetAttribute(gemm_presplit,  cudaFuncAttributeMaxDynamicSharedMemorySize, GEMM_SMEM);
    cudaFuncSetAttribute(gemm_fp16x2,    cudaFuncAttributeMaxDynamicSharedMemorySize, GEMM16_SMEM);
    cudaFuncSetAttribute(flash_attn_mma, cudaFuncAttributeMaxDynamicSharedMemorySize, ATTN_SMEM);

    const dim3 blk(256);

    // 1: hidden split
    convert_split<<<TOKENS * 1024 / 4 / 256, blk>>>(hidden, ah, al, TOKENS * 1024 / 4);
    // 2: Wo fp16 transpose
    transpose_f16<<<dim3(32, 32), blk>>>(Wo, wof, 1024);
    // 3: merged Wq/Wk/Wv transpose-split
    transpose_split3<<<dim3(64, 32), blk>>>(Wq, Wk, Wv, wth, wtl);
    // 4: fused QKV GEMM (ncu capture position)
    gemm_presplit<<<dim3(16, 32), blk, GEMM_SMEM>>>(ah, al, wth, wtl, qkv, 2048);
    // 5: RMSNorm + RoPE; K -> bf16 hi/lo, V -> fp16 transposed
    qkv_epilogue<<<TOKENS * 32 / 8, blk>>>(qkv, qg, kg, pos, q, kh, kl, vth);
    // 6: attention (smem-staged K/V)
    flash_attn_mma<<<dim3(SS_ / 128, BB * NH), blk, ATTN_SMEM>>>(q, kh, kl, vth, ao);
    // 7: AO fp16 split
    convert_split_f16<<<TOKENS * 1024 / 4 / 256, blk>>>(ao, aofh, aofl, TOKENS * 1024 / 4);
    // 8: O projection
    gemm_fp16x2<<<dim3(8, 32), blk, GEMM16_SMEM>>>(aofh, aofl, wof, out, 1024);
}